// round 1
// baseline (speedup 1.0000x reference)
#include <cuda_runtime.h>
#include <math.h>

#define N_TOK   2048
#define D_MODEL 1024
#define H_Q     16
#define H_KV    4
#define HD      64
#define REPEATS (H_Q / H_KV)   // 4
#define QDIM    (H_Q * HD)     // 1024
#define KVDIM   (H_KV * HD)    // 256
#define SCALE   0.125f         // 1/sqrt(64)

// Scratch (allocation-free rule: __device__ globals)
__device__ float g_Q[N_TOK * QDIM];   // 8 MB
__device__ float g_K[N_TOK * KVDIM];  // 2 MB
__device__ float g_V[N_TOK * KVDIM];  // 2 MB
__device__ float g_O[N_TOK * QDIM];   // 8 MB

// ---------------------------------------------------------------------------
// Tiled fp32 GEMM: C[M,Nc] = A[M,K] @ B[K,Nc]
// BM=BN=64, BK=32, 256 threads, 4x4 micro-tile per thread.
// Requires M,Nc % 64 == 0 and K % 32 == 0 (true for all calls here).
// ---------------------------------------------------------------------------
__global__ __launch_bounds__(256) void gemm64(
    const float* __restrict__ A, const float* __restrict__ B,
    float* __restrict__ C, int M, int Nc, int K)
{
    __shared__ float AsT[32][64];  // transposed A tile: AsT[k][m]
    __shared__ float Bs[32][64];   // Bs[k][n]

    const int tid = threadIdx.x;
    const int tx = tid & 15;        // 0..15 -> 4 output cols each
    const int ty = tid >> 4;        // 0..15 -> 4 output rows each
    const int rowBase = blockIdx.y * 64;
    const int colBase = blockIdx.x * 64;

    float acc[4][4] = {};

    for (int k0 = 0; k0 < K; k0 += 32) {
        // Load A tile (64 rows x 32 cols) transposed, and B tile (32 x 64).
        #pragma unroll
        for (int p = 0; p < 2; p++) {
            int idx = tid + p * 256;           // 0..511
            int ar = idx >> 3, ac4 = idx & 7;  // 64 rows x 8 float4
            float4 av = *(const float4*)&A[(size_t)(rowBase + ar) * K + k0 + ac4 * 4];
            AsT[ac4 * 4 + 0][ar] = av.x;
            AsT[ac4 * 4 + 1][ar] = av.y;
            AsT[ac4 * 4 + 2][ar] = av.z;
            AsT[ac4 * 4 + 3][ar] = av.w;

            int br = idx >> 4, bc4 = idx & 15; // 32 rows x 16 float4
            *(float4*)&Bs[br][bc4 * 4] =
                *(const float4*)&B[(size_t)(k0 + br) * Nc + colBase + bc4 * 4];
        }
        __syncthreads();

        #pragma unroll
        for (int kk = 0; kk < 32; kk++) {
            float4 a4 = *(const float4*)&AsT[kk][ty * 4];
            float4 b4 = *(const float4*)&Bs[kk][tx * 4];
            float a[4] = {a4.x, a4.y, a4.z, a4.w};
            float b[4] = {b4.x, b4.y, b4.z, b4.w};
            #pragma unroll
            for (int m = 0; m < 4; m++)
                #pragma unroll
                for (int n = 0; n < 4; n++)
                    acc[m][n] += a[m] * b[n];
        }
        __syncthreads();
    }

    #pragma unroll
    for (int m = 0; m < 4; m++) {
        float4 v = make_float4(acc[m][0], acc[m][1], acc[m][2], acc[m][3]);
        *(float4*)&C[(size_t)(rowBase + ty * 4 + m) * Nc + colBase + tx * 4] = v;
    }
}

// ---------------------------------------------------------------------------
// RoPE, applied in place on t[N_TOK, heads, HD] (interleaved real/imag pairs)
// ---------------------------------------------------------------------------
__global__ void rope_kernel(float* __restrict__ t,
                            const float* __restrict__ fcos,
                            const float* __restrict__ fsin,
                            int heads)
{
    int idx = blockIdx.x * blockDim.x + threadIdx.x;
    int total = N_TOK * heads * (HD / 2);
    if (idx >= total) return;
    int i = idx % (HD / 2);
    int h = (idx / (HD / 2)) % heads;
    int n = idx / ((HD / 2) * heads);

    float c = fcos[n * (HD / 2) + i];
    float s = fsin[n * (HD / 2) + i];
    float* base = t + ((size_t)n * heads + h) * HD;
    float tr = base[2 * i];
    float ti = base[2 * i + 1];
    base[2 * i]     = tr * c - ti * s;
    base[2 * i + 1] = tr * s + ti * c;
}

// ---------------------------------------------------------------------------
// Flash-style attention. Grid: (N_TOK/64, H_Q). Block: 64 threads.
// Thread i owns query row n0+i of head h: q and o accumulator in registers,
// K/V tiles broadcast from shared memory, online softmax.
// ---------------------------------------------------------------------------
__global__ __launch_bounds__(64) void attn_kernel()
{
    __shared__ float Ks[64][64];
    __shared__ float Vs[64][64];
    __shared__ float Ss[64][65];   // stride-65 pad: conflict-free row access

    const int h   = blockIdx.y;
    const int kvh = h / REPEATS;
    const int n0  = blockIdx.x * 64;
    const int i   = threadIdx.x;

    float q[HD];
    {
        const float4* qp = (const float4*)(g_Q + ((size_t)(n0 + i) * H_Q + h) * HD);
        #pragma unroll
        for (int d4 = 0; d4 < HD / 4; d4++) {
            float4 v = qp[d4];
            q[d4 * 4 + 0] = v.x; q[d4 * 4 + 1] = v.y;
            q[d4 * 4 + 2] = v.z; q[d4 * 4 + 3] = v.w;
        }
    }

    float m = -INFINITY, l = 0.0f;
    float o[HD];
    #pragma unroll
    for (int d = 0; d < HD; d++) o[d] = 0.0f;

    for (int t0 = 0; t0 < N_TOK; t0 += 64) {
        __syncthreads();   // previous tile fully consumed
        {
            const float4* kp = (const float4*)(g_K + ((size_t)(t0 + i) * H_KV + kvh) * HD);
            const float4* vp = (const float4*)(g_V + ((size_t)(t0 + i) * H_KV + kvh) * HD);
            float4* krow = (float4*)Ks[i];
            float4* vrow = (float4*)Vs[i];
            #pragma unroll
            for (int d4 = 0; d4 < HD / 4; d4++) {
                krow[d4] = kp[d4];
                vrow[d4] = vp[d4];
            }
        }
        __syncthreads();

        // Pass 1: scores for my row over this key tile
        float tmax = -INFINITY;
        for (int j = 0; j < 64; j++) {
            const float4* kr = (const float4*)Ks[j];
            float s = 0.0f;
            #pragma unroll
            for (int d4 = 0; d4 < HD / 4; d4++) {
                float4 kv = kr[d4];
                s += q[d4 * 4 + 0] * kv.x + q[d4 * 4 + 1] * kv.y
                   + q[d4 * 4 + 2] * kv.z + q[d4 * 4 + 3] * kv.w;
            }
            s *= SCALE;
            Ss[i][j] = s;
            tmax = fmaxf(tmax, s);
        }

        float mnew = fmaxf(m, tmax);
        float corr = __expf(m - mnew);   // exp(-inf) = 0 on first tile
        l *= corr;
        #pragma unroll
        for (int d = 0; d < HD; d++) o[d] *= corr;

        // Pass 2: exp + accumulate into o
        for (int j = 0; j < 64; j++) {
            float p = __expf(Ss[i][j] - mnew);
            l += p;
            const float4* vr = (const float4*)Vs[j];
            #pragma unroll
            for (int d4 = 0; d4 < HD / 4; d4++) {
                float4 vv = vr[d4];
                o[d4 * 4 + 0] += p * vv.x;
                o[d4 * 4 + 1] += p * vv.y;
                o[d4 * 4 + 2] += p * vv.z;
                o[d4 * 4 + 3] += p * vv.w;
            }
        }
        m = mnew;
    }

    float inv = 1.0f / l;
    float4* op = (float4*)(g_O + ((size_t)(n0 + i) * H_Q + h) * HD);
    #pragma unroll
    for (int d4 = 0; d4 < HD / 4; d4++) {
        float4 v = make_float4(o[d4 * 4 + 0] * inv, o[d4 * 4 + 1] * inv,
                               o[d4 * 4 + 2] * inv, o[d4 * 4 + 3] * inv);
        op[d4] = v;
    }
}

// ---------------------------------------------------------------------------
// Launcher
// ---------------------------------------------------------------------------
extern "C" void kernel_launch(void* const* d_in, const int* in_sizes, int n_in,
                              void* d_out, int out_size)
{
    const float* x    = (const float*)d_in[0];
    const float* fcos = (const float*)d_in[1];
    const float* fsin = (const float*)d_in[2];
    const float* Wq   = (const float*)d_in[3];
    const float* Wk   = (const float*)d_in[4];
    const float* Wv   = (const float*)d_in[5];
    const float* Wo   = (const float*)d_in[6];
    float* out = (float*)d_out;

    static float *pQ = nullptr, *pK = nullptr, *pV = nullptr, *pO = nullptr;
    if (!pQ) {
        cudaGetSymbolAddress((void**)&pQ, g_Q);
        cudaGetSymbolAddress((void**)&pK, g_K);
        cudaGetSymbolAddress((void**)&pV, g_V);
        cudaGetSymbolAddress((void**)&pO, g_O);
    }

    // QKV projections
    gemm64<<<dim3(QDIM / 64,  N_TOK / 64), 256>>>(x, Wq, pQ, N_TOK, QDIM,  D_MODEL);
    gemm64<<<dim3(KVDIM / 64, N_TOK / 64), 256>>>(x, Wk, pK, N_TOK, KVDIM, D_MODEL);
    gemm64<<<dim3(KVDIM / 64, N_TOK / 64), 256>>>(x, Wv, pV, N_TOK, KVDIM, D_MODEL);

    // RoPE on Q and K
    {
        int totQ = N_TOK * H_Q * (HD / 2);
        int totK = N_TOK * H_KV * (HD / 2);
        rope_kernel<<<(totQ + 255) / 256, 256>>>(pQ, fcos, fsin, H_Q);
        rope_kernel<<<(totK + 255) / 256, 256>>>(pK, fcos, fsin, H_KV);
    }

    // Attention
    attn_kernel<<<dim3(N_TOK / 64, H_Q), 64>>>();

    // Output projection
    gemm64<<<dim3(D_MODEL / 64, N_TOK / 64), 256>>>(pO, Wo, out, N_TOK, D_MODEL, QDIM);
}

// round 2
// speedup vs baseline: 3.8378x; 3.8378x over previous
#include <cuda_runtime.h>
#include <math.h>
#include <stdint.h>

#define N_TOK   2048
#define D_MODEL 1024
#define H_Q     16
#define H_KV    4
#define HD      64
#define REPEATS (H_Q / H_KV)   // 4
#define QDIM    (H_Q * HD)     // 1024
#define KVDIM   (H_KV * HD)    // 256
#define SCALE   0.125f         // 1/sqrt(64)

// Scratch (allocation-free rule: __device__ globals)
__device__ float g_Q[N_TOK * QDIM];   // 8 MB
__device__ float g_K[N_TOK * KVDIM];  // 2 MB
__device__ float g_V[N_TOK * KVDIM];  // 2 MB
__device__ float g_O[N_TOK * QDIM];   // 8 MB

// ---------------------------------------------------------------------------
// tf32 helpers
// ---------------------------------------------------------------------------
__device__ __forceinline__ uint32_t f2tf32(float f) {
    uint32_t r;
    asm("cvt.rna.tf32.f32 %0, %1;" : "=r"(r) : "f"(f));
    return r;
}

// D += A*B, m16n8k8, A row-major frags, B col-major frags, fp32 accum
__device__ __forceinline__ void mma_tf32(float* d, const uint32_t* a, const uint32_t* b) {
    asm volatile(
        "mma.sync.aligned.m16n8k8.row.col.f32.tf32.tf32.f32 "
        "{%0,%1,%2,%3}, {%4,%5,%6,%7}, {%8,%9}, {%0,%1,%2,%3};"
        : "+f"(d[0]), "+f"(d[1]), "+f"(d[2]), "+f"(d[3])
        : "r"(a[0]), "r"(a[1]), "r"(a[2]), "r"(a[3]),
          "r"(b[0]), "r"(b[1]));
}

// ---------------------------------------------------------------------------
// tf32 tensor-core GEMM: C[M,Nc] = A[M,K] @ B[K,Nc], all row-major fp32.
// Block tile 128x128x32, 256 threads (8 warps), warp tile 64(m)x32(n).
// Requires M%128==0, Nc%128==0, K%32==0.
// ---------------------------------------------------------------------------
#define LDA 36   // A smem [m][k] pad: frag bank = (4g+t) -> conflict-free
#define LDB 136  // B smem [k][n] pad: frag bank = (8t+g) -> conflict-free

__global__ __launch_bounds__(256) void gemm_tf32(
    const float* __restrict__ A, const float* __restrict__ B,
    float* __restrict__ C, int M, int Nc, int K)
{
    __shared__ uint32_t As[128 * LDA];
    __shared__ uint32_t Bs[32 * LDB];

    const int tid  = threadIdx.x;
    const int lane = tid & 31;
    const int w    = tid >> 5;
    const int g    = lane >> 2;   // group id 0..7
    const int t    = lane & 3;    // thread-in-group 0..3
    const int wm   = w >> 2;      // 0..1 -> 64 rows each
    const int wn   = w & 3;       // 0..3 -> 32 cols each
    const int rowBase = blockIdx.y * 128;
    const int colBase = blockIdx.x * 128;

    float acc[4][4][4];
    #pragma unroll
    for (int mi = 0; mi < 4; mi++)
        #pragma unroll
        for (int nj = 0; nj < 4; nj++)
            #pragma unroll
            for (int r = 0; r < 4; r++) acc[mi][nj][r] = 0.0f;

    for (int k0 = 0; k0 < K; k0 += 32) {
        // Load + convert A tile (128x32) and B tile (32x128)
        #pragma unroll
        for (int p = 0; p < 4; p++) {
            int idx = tid + p * 256;            // 0..1023
            int r = idx >> 3, c4 = (idx & 7) << 2;
            float4 v = *(const float4*)&A[(size_t)(rowBase + r) * K + k0 + c4];
            uint4 u = make_uint4(f2tf32(v.x), f2tf32(v.y), f2tf32(v.z), f2tf32(v.w));
            *(uint4*)&As[r * LDA + c4] = u;
        }
        #pragma unroll
        for (int p = 0; p < 4; p++) {
            int idx = tid + p * 256;
            int r = idx >> 5, c4 = (idx & 31) << 2;
            float4 v = *(const float4*)&B[(size_t)(k0 + r) * Nc + colBase + c4];
            uint4 u = make_uint4(f2tf32(v.x), f2tf32(v.y), f2tf32(v.z), f2tf32(v.w));
            *(uint4*)&Bs[r * LDB + c4] = u;
        }
        __syncthreads();

        #pragma unroll
        for (int kk = 0; kk < 4; kk++) {
            const int kb = kk * 8;
            uint32_t af[4][4];
            #pragma unroll
            for (int mi = 0; mi < 4; mi++) {
                int mr = wm * 64 + mi * 16;
                af[mi][0] = As[(mr + g)     * LDA + kb + t];
                af[mi][1] = As[(mr + g + 8) * LDA + kb + t];
                af[mi][2] = As[(mr + g)     * LDA + kb + t + 4];
                af[mi][3] = As[(mr + g + 8) * LDA + kb + t + 4];
            }
            #pragma unroll
            for (int nj = 0; nj < 4; nj++) {
                int nc = wn * 32 + nj * 8;
                uint32_t bf[2];
                bf[0] = Bs[(kb + t)     * LDB + nc + g];
                bf[1] = Bs[(kb + t + 4) * LDB + nc + g];
                #pragma unroll
                for (int mi = 0; mi < 4; mi++)
                    mma_tf32(acc[mi][nj], af[mi], bf);
            }
        }
        __syncthreads();
    }

    // Epilogue
    #pragma unroll
    for (int mi = 0; mi < 4; mi++) {
        int row = rowBase + wm * 64 + mi * 16 + g;
        #pragma unroll
        for (int nj = 0; nj < 4; nj++) {
            int col = colBase + wn * 32 + nj * 8 + 2 * t;
            *(float2*)&C[(size_t)row * Nc + col] =
                make_float2(acc[mi][nj][0], acc[mi][nj][1]);
            *(float2*)&C[(size_t)(row + 8) * Nc + col] =
                make_float2(acc[mi][nj][2], acc[mi][nj][3]);
        }
    }
}

// ---------------------------------------------------------------------------
// RoPE in place on t[N_TOK, heads, HD]
// ---------------------------------------------------------------------------
__global__ void rope_kernel(float* __restrict__ t,
                            const float* __restrict__ fcos,
                            const float* __restrict__ fsin,
                            int heads)
{
    int idx = blockIdx.x * blockDim.x + threadIdx.x;
    int total = N_TOK * heads * (HD / 2);
    if (idx >= total) return;
    int i = idx % (HD / 2);
    int h = (idx / (HD / 2)) % heads;
    int n = idx / ((HD / 2) * heads);

    float c = fcos[n * (HD / 2) + i];
    float s = fsin[n * (HD / 2) + i];
    float* base = t + ((size_t)n * heads + h) * HD;
    float tr = base[2 * i];
    float ti = base[2 * i + 1];
    base[2 * i]     = tr * c - ti * s;
    base[2 * i + 1] = tr * s + ti * c;
}

// ---------------------------------------------------------------------------
// FlashAttention-2 style tf32 mma attention.
// Grid (N_TOK/64, H_Q), 128 threads (4 warps), warp owns 16 query rows.
// K/P share one smem buffer (ld 68), V in second (ld 72) — pads chosen so all
// fragment LDS are bank-conflict-free.
// ---------------------------------------------------------------------------
#define LDK 68
#define LDV 72

__global__ __launch_bounds__(128) void attn_mma()
{
    __shared__ uint32_t KP[64 * LDK];  // K tile (tf32 bits), reused as P
    __shared__ uint32_t Vs[64 * LDV];  // V tile (tf32 bits)

    const int h   = blockIdx.y;
    const int kvh = h / REPEATS;
    const int n0  = blockIdx.x * 64;
    const int tid = threadIdx.x;
    const int lane = tid & 31;
    const int w    = tid >> 5;
    const int g    = lane >> 2;
    const int t    = lane & 3;

    // Q fragments, register-resident, pre-scaled, tf32
    uint32_t qf[8][4];
    {
        const float* q0 = g_Q + (size_t)(n0 + w * 16) * QDIM + h * HD;
        #pragma unroll
        for (int kf = 0; kf < 8; kf++) {
            qf[kf][0] = f2tf32(q0[(size_t)g       * QDIM + kf * 8 + t]     * SCALE);
            qf[kf][1] = f2tf32(q0[(size_t)(g + 8) * QDIM + kf * 8 + t]     * SCALE);
            qf[kf][2] = f2tf32(q0[(size_t)g       * QDIM + kf * 8 + t + 4] * SCALE);
            qf[kf][3] = f2tf32(q0[(size_t)(g + 8) * QDIM + kf * 8 + t + 4] * SCALE);
        }
    }

    float m0 = -INFINITY, m1 = -INFINITY, l0 = 0.0f, l1 = 0.0f;
    float o[8][4];
    #pragma unroll
    for (int j = 0; j < 8; j++)
        #pragma unroll
        for (int r = 0; r < 4; r++) o[j][r] = 0.0f;

    for (int t0 = 0; t0 < N_TOK; t0 += 64) {
        __syncthreads();   // prior P/V reads complete before overwrite
        // Load K,V tiles (convert to tf32 at store)
        #pragma unroll
        for (int p = 0; p < 8; p++) {
            int idx = tid + p * 128;           // 0..1023
            int r = idx >> 4, c4 = (idx & 15) << 2;
            float4 kv = *(const float4*)&g_K[(size_t)(t0 + r) * KVDIM + kvh * HD + c4];
            *(uint4*)&KP[r * LDK + c4] =
                make_uint4(f2tf32(kv.x), f2tf32(kv.y), f2tf32(kv.z), f2tf32(kv.w));
            float4 vv = *(const float4*)&g_V[(size_t)(t0 + r) * KVDIM + kvh * HD + c4];
            *(uint4*)&Vs[r * LDV + c4] =
                make_uint4(f2tf32(vv.x), f2tf32(vv.y), f2tf32(vv.z), f2tf32(vv.w));
        }
        __syncthreads();

        // S = (Q*scale) @ K^T : s[j] covers keys j*8..j*8+7
        float s[8][4];
        #pragma unroll
        for (int j = 0; j < 8; j++)
            #pragma unroll
            for (int r = 0; r < 4; r++) s[j][r] = 0.0f;

        #pragma unroll
        for (int kf = 0; kf < 8; kf++) {
            #pragma unroll
            for (int j = 0; j < 8; j++) {
                uint32_t bf[2];
                bf[0] = KP[(j * 8 + g) * LDK + kf * 8 + t];
                bf[1] = KP[(j * 8 + g) * LDK + kf * 8 + t + 4];
                mma_tf32(s[j], qf[kf], bf);
            }
        }
        __syncthreads();   // all warps done reading K before P overwrite

        // Online softmax (rows g -> idx0, g+8 -> idx1)
        float tm0 = -INFINITY, tm1 = -INFINITY;
        #pragma unroll
        for (int j = 0; j < 8; j++) {
            tm0 = fmaxf(tm0, fmaxf(s[j][0], s[j][1]));
            tm1 = fmaxf(tm1, fmaxf(s[j][2], s[j][3]));
        }
        #pragma unroll
        for (int off = 1; off < 4; off <<= 1) {
            tm0 = fmaxf(tm0, __shfl_xor_sync(0xFFFFFFFF, tm0, off));
            tm1 = fmaxf(tm1, __shfl_xor_sync(0xFFFFFFFF, tm1, off));
        }
        float mn0 = fmaxf(m0, tm0), mn1 = fmaxf(m1, tm1);
        float c0 = __expf(m0 - mn0), c1 = __expf(m1 - mn1);
        l0 *= c0; l1 *= c1;
        #pragma unroll
        for (int j = 0; j < 8; j++) {
            o[j][0] *= c0; o[j][1] *= c0;
            o[j][2] *= c1; o[j][3] *= c1;
        }
        m0 = mn0; m1 = mn1;

        // P = exp(S - m), written tf32 into KP rows owned by this warp
        const int pr0 = (w * 16 + g) * LDK;
        const int pr1 = (w * 16 + g + 8) * LDK;
        #pragma unroll
        for (int j = 0; j < 8; j++) {
            uint32_t u00 = f2tf32(__expf(s[j][0] - mn0));
            uint32_t u01 = f2tf32(__expf(s[j][1] - mn0));
            uint32_t u10 = f2tf32(__expf(s[j][2] - mn1));
            uint32_t u11 = f2tf32(__expf(s[j][3] - mn1));
            l0 += __uint_as_float(u00) + __uint_as_float(u01);
            l1 += __uint_as_float(u10) + __uint_as_float(u11);
            *(uint2*)&KP[pr0 + j * 8 + 2 * t] = make_uint2(u00, u01);
            *(uint2*)&KP[pr1 + j * 8 + 2 * t] = make_uint2(u10, u11);
        }
        __syncwarp();

        // O += P @ V
        #pragma unroll
        for (int ks = 0; ks < 8; ks++) {
            uint32_t pa[4];
            pa[0] = KP[(w * 16 + g)     * LDK + ks * 8 + t];
            pa[1] = KP[(w * 16 + g + 8) * LDK + ks * 8 + t];
            pa[2] = KP[(w * 16 + g)     * LDK + ks * 8 + t + 4];
            pa[3] = KP[(w * 16 + g + 8) * LDK + ks * 8 + t + 4];
            #pragma unroll
            for (int j = 0; j < 8; j++) {
                uint32_t bf[2];
                bf[0] = Vs[(ks * 8 + t)     * LDV + j * 8 + g];
                bf[1] = Vs[(ks * 8 + t + 4) * LDV + j * 8 + g];
                mma_tf32(o[j], pa, bf);
            }
        }
    }

    // Final normalize + write
    #pragma unroll
    for (int off = 1; off < 4; off <<= 1) {
        l0 += __shfl_xor_sync(0xFFFFFFFF, l0, off);
        l1 += __shfl_xor_sync(0xFFFFFFFF, l1, off);
    }
    float inv0 = 1.0f / l0, inv1 = 1.0f / l1;
    const int row0 = n0 + w * 16 + g;
    float* op0 = g_O + (size_t)row0 * QDIM + h * HD;
    float* op1 = g_O + (size_t)(row0 + 8) * QDIM + h * HD;
    #pragma unroll
    for (int j = 0; j < 8; j++) {
        *(float2*)&op0[j * 8 + 2 * t] = make_float2(o[j][0] * inv0, o[j][1] * inv0);
        *(float2*)&op1[j * 8 + 2 * t] = make_float2(o[j][2] * inv1, o[j][3] * inv1);
    }
}

// ---------------------------------------------------------------------------
// Launcher
// ---------------------------------------------------------------------------
extern "C" void kernel_launch(void* const* d_in, const int* in_sizes, int n_in,
                              void* d_out, int out_size)
{
    const float* x    = (const float*)d_in[0];
    const float* fcos = (const float*)d_in[1];
    const float* fsin = (const float*)d_in[2];
    const float* Wq   = (const float*)d_in[3];
    const float* Wk   = (const float*)d_in[4];
    const float* Wv   = (const float*)d_in[5];
    const float* Wo   = (const float*)d_in[6];
    float* out = (float*)d_out;

    static float *pQ = nullptr, *pK = nullptr, *pV = nullptr, *pO = nullptr;
    if (!pQ) {
        cudaGetSymbolAddress((void**)&pQ, g_Q);
        cudaGetSymbolAddress((void**)&pK, g_K);
        cudaGetSymbolAddress((void**)&pV, g_V);
        cudaGetSymbolAddress((void**)&pO, g_O);
    }

    // QKV projections (tensor core, tf32)
    gemm_tf32<<<dim3(QDIM / 128,  N_TOK / 128), 256>>>(x, Wq, pQ, N_TOK, QDIM,  D_MODEL);
    gemm_tf32<<<dim3(KVDIM / 128, N_TOK / 128), 256>>>(x, Wk, pK, N_TOK, KVDIM, D_MODEL);
    gemm_tf32<<<dim3(KVDIM / 128, N_TOK / 128), 256>>>(x, Wv, pV, N_TOK, KVDIM, D_MODEL);

    // RoPE
    {
        int totQ = N_TOK * H_Q * (HD / 2);
        int totK = N_TOK * H_KV * (HD / 2);
        rope_kernel<<<(totQ + 255) / 256, 256>>>(pQ, fcos, fsin, H_Q);
        rope_kernel<<<(totK + 255) / 256, 256>>>(pK, fcos, fsin, H_KV);
    }

    // Attention (tensor core, tf32)
    attn_mma<<<dim3(N_TOK / 64, H_Q), 128>>>();

    // Output projection
    gemm_tf32<<<dim3(D_MODEL / 128, N_TOK / 128), 256>>>(pO, Wo, out, N_TOK, D_MODEL, QDIM);
}

// round 3
// speedup vs baseline: 4.6717x; 1.2173x over previous
#include <cuda_runtime.h>
#include <math.h>
#include <stdint.h>

#define N_TOK   2048
#define D_MODEL 1024
#define H_Q     16
#define H_KV    4
#define HD      64
#define REPEATS (H_Q / H_KV)   // 4
#define QDIM    (H_Q * HD)     // 1024
#define KVDIM   (H_KV * HD)    // 256
#define SCALE   0.125f         // 1/sqrt(64)

// Scratch (allocation-free rule: __device__ globals)
__device__ float g_Q[N_TOK * QDIM];   // 8 MB
__device__ float g_K[N_TOK * KVDIM];  // 2 MB
__device__ float g_V[N_TOK * KVDIM];  // 2 MB
__device__ float g_O[N_TOK * QDIM];   // 8 MB

// ---------------------------------------------------------------------------
// tf32 helpers
// ---------------------------------------------------------------------------
__device__ __forceinline__ uint32_t f2tf32(float f) {
    uint32_t r;
    asm("cvt.rna.tf32.f32 %0, %1;" : "=r"(r) : "f"(f));
    return r;
}

__device__ __forceinline__ void mma_tf32(float* d, const uint32_t* a, const uint32_t* b) {
    asm volatile(
        "mma.sync.aligned.m16n8k8.row.col.f32.tf32.tf32.f32 "
        "{%0,%1,%2,%3}, {%4,%5,%6,%7}, {%8,%9}, {%0,%1,%2,%3};"
        : "+f"(d[0]), "+f"(d[1]), "+f"(d[2]), "+f"(d[3])
        : "r"(a[0]), "r"(a[1]), "r"(a[2]), "r"(a[3]),
          "r"(b[0]), "r"(b[1]));
}

// ---------------------------------------------------------------------------
// Templated tf32 GEMM with register-staged prefetch and optional fused RoPE.
// C[M,Nc] = A[M,K] @ B[K,Nc]; 256 threads; BK=32; warp grid WGM x WGN.
// If fcos != nullptr, applies RoPE to output pairs (col even/odd), using
// per-row (token) angle tables of width HD/2, head-local index (col&63)>>1.
// ---------------------------------------------------------------------------
#define LDA 36   // A smem [m][k] pad: frag bank = (4g+t) -> conflict-free

template<int BM, int BN, int WGM, int WGN>
__global__ __launch_bounds__(256, 2) void gemm_tf32(
    const float* __restrict__ A, const float* __restrict__ B,
    float* __restrict__ C, int M, int Nc, int K,
    const float* __restrict__ fcos, const float* __restrict__ fsin)
{
    constexpr int LDB = BN + 8;          // B smem [k][n] pad: bank (8t+g)
    constexpr int MI  = BM / WGM / 16;   // m16 blocks per warp
    constexpr int NJ  = BN / WGN / 8;    // n8 blocks per warp
    constexpr int AIT = BM * 8 / 256;    // float4 A loads per thread
    constexpr int BIT = BN / 32;         // float4 B loads per thread
    constexpr int BC4 = BN / 4;          // float4s per B row

    __shared__ uint32_t As[BM * LDA];
    __shared__ uint32_t Bs[32 * LDB];

    const int tid  = threadIdx.x;
    const int lane = tid & 31;
    const int w    = tid >> 5;
    const int g    = lane >> 2;
    const int t    = lane & 3;
    const int wm   = w / WGN;
    const int wn   = w % WGN;
    const int rowBase = blockIdx.y * BM;
    const int colBase = blockIdx.x * BN;

    float acc[MI][NJ][4];
    #pragma unroll
    for (int mi = 0; mi < MI; mi++)
        #pragma unroll
        for (int nj = 0; nj < NJ; nj++)
            #pragma unroll
            for (int r = 0; r < 4; r++) acc[mi][nj][r] = 0.0f;

    float4 aReg[AIT], bReg[BIT];

    // Prologue: fetch tile k0=0 into registers
    #pragma unroll
    for (int p = 0; p < AIT; p++) {
        int idx = tid + p * 256;
        int r = idx >> 3, c4 = (idx & 7) << 2;
        aReg[p] = *(const float4*)&A[(size_t)(rowBase + r) * K + c4];
    }
    #pragma unroll
    for (int p = 0; p < BIT; p++) {
        int idx = tid + p * 256;
        int r = idx / BC4, c4 = (idx % BC4) << 2;
        bReg[p] = *(const float4*)&B[(size_t)r * Nc + colBase + c4];
    }

    for (int k0 = 0; k0 < K; k0 += 32) {
        // Commit staged registers to smem (tf32 convert at store)
        #pragma unroll
        for (int p = 0; p < AIT; p++) {
            int idx = tid + p * 256;
            int r = idx >> 3, c4 = (idx & 7) << 2;
            *(uint4*)&As[r * LDA + c4] = make_uint4(
                f2tf32(aReg[p].x), f2tf32(aReg[p].y),
                f2tf32(aReg[p].z), f2tf32(aReg[p].w));
        }
        #pragma unroll
        for (int p = 0; p < BIT; p++) {
            int idx = tid + p * 256;
            int r = idx / BC4, c4 = (idx % BC4) << 2;
            *(uint4*)&Bs[r * LDB + c4] = make_uint4(
                f2tf32(bReg[p].x), f2tf32(bReg[p].y),
                f2tf32(bReg[p].z), f2tf32(bReg[p].w));
        }
        __syncthreads();

        // Prefetch next tile (overlaps the mma work below)
        if (k0 + 32 < K) {
            #pragma unroll
            for (int p = 0; p < AIT; p++) {
                int idx = tid + p * 256;
                int r = idx >> 3, c4 = (idx & 7) << 2;
                aReg[p] = *(const float4*)&A[(size_t)(rowBase + r) * K + k0 + 32 + c4];
            }
            #pragma unroll
            for (int p = 0; p < BIT; p++) {
                int idx = tid + p * 256;
                int r = idx / BC4, c4 = (idx % BC4) << 2;
                bReg[p] = *(const float4*)&B[(size_t)(k0 + 32 + r) * Nc + colBase + c4];
            }
        }

        #pragma unroll
        for (int kk = 0; kk < 4; kk++) {
            const int kb = kk * 8;
            uint32_t af[MI][4];
            #pragma unroll
            for (int mi = 0; mi < MI; mi++) {
                int mr = wm * (BM / WGM) + mi * 16;
                af[mi][0] = As[(mr + g)     * LDA + kb + t];
                af[mi][1] = As[(mr + g + 8) * LDA + kb + t];
                af[mi][2] = As[(mr + g)     * LDA + kb + t + 4];
                af[mi][3] = As[(mr + g + 8) * LDA + kb + t + 4];
            }
            #pragma unroll
            for (int nj = 0; nj < NJ; nj++) {
                int nc = wn * (BN / WGN) + nj * 8;
                uint32_t bf[2];
                bf[0] = Bs[(kb + t)     * LDB + nc + g];
                bf[1] = Bs[(kb + t + 4) * LDB + nc + g];
                #pragma unroll
                for (int mi = 0; mi < MI; mi++)
                    mma_tf32(acc[mi][nj], af[mi], bf);
            }
        }
        __syncthreads();
    }

    // Epilogue (optional fused RoPE: each thread owns adjacent col pair 2t,2t+1)
    #pragma unroll
    for (int mi = 0; mi < MI; mi++) {
        int row = rowBase + wm * (BM / WGM) + mi * 16 + g;
        #pragma unroll
        for (int nj = 0; nj < NJ; nj++) {
            int col = colBase + wn * (BN / WGN) + nj * 8 + 2 * t;
            float v0 = acc[mi][nj][0], v1 = acc[mi][nj][1];
            float v2 = acc[mi][nj][2], v3 = acc[mi][nj][3];
            if (fcos) {
                int i = (col & (HD - 1)) >> 1;
                float c0 = fcos[row * (HD / 2) + i];
                float s0 = fsin[row * (HD / 2) + i];
                float c1 = fcos[(row + 8) * (HD / 2) + i];
                float s1 = fsin[(row + 8) * (HD / 2) + i];
                float r0 = v0 * c0 - v1 * s0, i0 = v0 * s0 + v1 * c0;
                float r1 = v2 * c1 - v3 * s1, i1 = v2 * s1 + v3 * c1;
                v0 = r0; v1 = i0; v2 = r1; v3 = i1;
            }
            *(float2*)&C[(size_t)row * Nc + col]       = make_float2(v0, v1);
            *(float2*)&C[(size_t)(row + 8) * Nc + col] = make_float2(v2, v3);
        }
    }
}

// ---------------------------------------------------------------------------
// FlashAttention-2 tf32 mma attention, KV shared across 4 query heads.
// Grid (N_TOK/64, H_KV), 512 threads (16 warps).
// Warp w: head = kvh*4 + (w>>2), query rows n0 + (w&3)*16 .. +15.
// P never touches smem: D-frag -> A-frag via register shuffle permute.
// ---------------------------------------------------------------------------
#define LDK 68   // K frag bank = (4g+t)
#define LDV 72   // V frag bank = (8t+g)

__global__ __launch_bounds__(512) void attn_mma()
{
    __shared__ uint32_t Ks[64 * LDK];
    __shared__ uint32_t Vs[64 * LDV];

    const int kvh = blockIdx.y;
    const int n0  = blockIdx.x * 64;
    const int tid = threadIdx.x;
    const int lane = tid & 31;
    const int w    = tid >> 5;
    const int g    = lane >> 2;
    const int t    = lane & 3;
    const int h    = kvh * REPEATS + (w >> 2);
    const int qr0  = n0 + (w & 3) * 16;

    // Q fragments, register-resident, pre-scaled, tf32
    uint32_t qf[8][4];
    {
        const float* q0 = g_Q + (size_t)qr0 * QDIM + h * HD;
        #pragma unroll
        for (int kf = 0; kf < 8; kf++) {
            qf[kf][0] = f2tf32(q0[(size_t)g       * QDIM + kf * 8 + t]     * SCALE);
            qf[kf][1] = f2tf32(q0[(size_t)(g + 8) * QDIM + kf * 8 + t]     * SCALE);
            qf[kf][2] = f2tf32(q0[(size_t)g       * QDIM + kf * 8 + t + 4] * SCALE);
            qf[kf][3] = f2tf32(q0[(size_t)(g + 8) * QDIM + kf * 8 + t + 4] * SCALE);
        }
    }

    float m0 = -INFINITY, m1 = -INFINITY, l0 = 0.0f, l1 = 0.0f;
    float o[8][4];
    #pragma unroll
    for (int j = 0; j < 8; j++)
        #pragma unroll
        for (int r = 0; r < 4; r++) o[j][r] = 0.0f;

    const int srcA = (lane & 28) | (t >> 1);
    const int srcB = srcA | 2;
    const bool oddT = (t & 1);

    for (int t0 = 0; t0 < N_TOK; t0 += 64) {
        __syncthreads();   // prior tile fully consumed
        // Load K,V tiles (tf32 convert at store): 64 rows x 16 float4 each
        #pragma unroll
        for (int p = 0; p < 2; p++) {
            int idx = tid + p * 512;           // 0..1023
            int r = idx >> 4, c4 = (idx & 15) << 2;
            float4 kv = *(const float4*)&g_K[(size_t)(t0 + r) * KVDIM + kvh * HD + c4];
            *(uint4*)&Ks[r * LDK + c4] =
                make_uint4(f2tf32(kv.x), f2tf32(kv.y), f2tf32(kv.z), f2tf32(kv.w));
            float4 vv = *(const float4*)&g_V[(size_t)(t0 + r) * KVDIM + kvh * HD + c4];
            *(uint4*)&Vs[r * LDV + c4] =
                make_uint4(f2tf32(vv.x), f2tf32(vv.y), f2tf32(vv.z), f2tf32(vv.w));
        }
        __syncthreads();

        // S = (Q*scale) @ K^T
        float s[8][4];
        #pragma unroll
        for (int j = 0; j < 8; j++)
            #pragma unroll
            for (int r = 0; r < 4; r++) s[j][r] = 0.0f;
        #pragma unroll
        for (int kf = 0; kf < 8; kf++) {
            #pragma unroll
            for (int j = 0; j < 8; j++) {
                uint32_t bf[2];
                bf[0] = Ks[(j * 8 + g) * LDK + kf * 8 + t];
                bf[1] = Ks[(j * 8 + g) * LDK + kf * 8 + t + 4];
                mma_tf32(s[j], qf[kf], bf);
            }
        }

        // Online softmax (row g -> 0/1, row g+8 -> 2/3)
        float tm0 = -INFINITY, tm1 = -INFINITY;
        #pragma unroll
        for (int j = 0; j < 8; j++) {
            tm0 = fmaxf(tm0, fmaxf(s[j][0], s[j][1]));
            tm1 = fmaxf(tm1, fmaxf(s[j][2], s[j][3]));
        }
        #pragma unroll
        for (int off = 1; off < 4; off <<= 1) {
            tm0 = fmaxf(tm0, __shfl_xor_sync(0xFFFFFFFF, tm0, off));
            tm1 = fmaxf(tm1, __shfl_xor_sync(0xFFFFFFFF, tm1, off));
        }
        float mn0 = fmaxf(m0, tm0), mn1 = fmaxf(m1, tm1);
        float c0 = __expf(m0 - mn0), c1 = __expf(m1 - mn1);
        l0 *= c0; l1 *= c1;
        #pragma unroll
        for (int j = 0; j < 8; j++) {
            o[j][0] *= c0; o[j][1] *= c0;
            o[j][2] *= c1; o[j][3] *= c1;
        }
        m0 = mn0; m1 = mn1;

        // P = exp(S-m) in D-frag layout (tf32 bits), then permute to A-frags:
        // A-frag col t (block-local) lives in lane (lane&28)|(t>>1), elem t&1.
        uint32_t pa[8][4];
        #pragma unroll
        for (int j = 0; j < 8; j++) {
            float p00 = __expf(s[j][0] - mn0), p01 = __expf(s[j][1] - mn0);
            float p10 = __expf(s[j][2] - mn1), p11 = __expf(s[j][3] - mn1);
            l0 += p00 + p01;
            l1 += p10 + p11;
            uint32_t u00 = f2tf32(p00), u01 = f2tf32(p01);
            uint32_t u10 = f2tf32(p10), u11 = f2tf32(p11);

            uint32_t lo, hi;
            lo = __shfl_sync(0xFFFFFFFF, u00, srcA);
            hi = __shfl_sync(0xFFFFFFFF, u01, srcA);
            pa[j][0] = oddT ? hi : lo;                 // P(g, t)
            lo = __shfl_sync(0xFFFFFFFF, u00, srcB);
            hi = __shfl_sync(0xFFFFFFFF, u01, srcB);
            pa[j][2] = oddT ? hi : lo;                 // P(g, t+4)
            lo = __shfl_sync(0xFFFFFFFF, u10, srcA);
            hi = __shfl_sync(0xFFFFFFFF, u11, srcA);
            pa[j][1] = oddT ? hi : lo;                 // P(g+8, t)
            lo = __shfl_sync(0xFFFFFFFF, u10, srcB);
            hi = __shfl_sync(0xFFFFFFFF, u11, srcB);
            pa[j][3] = oddT ? hi : lo;                 // P(g+8, t+4)
        }

        // O += P @ V   (pa[kb] covers keys kb*8..kb*8+7)
        #pragma unroll
        for (int kb = 0; kb < 8; kb++) {
            #pragma unroll
            for (int j = 0; j < 8; j++) {
                uint32_t bf[2];
                bf[0] = Vs[(kb * 8 + t)     * LDV + j * 8 + g];
                bf[1] = Vs[(kb * 8 + t + 4) * LDV + j * 8 + g];
                mma_tf32(o[j], pa[kb], bf);
            }
        }
    }

    // Final normalize + write
    #pragma unroll
    for (int off = 1; off < 4; off <<= 1) {
        l0 += __shfl_xor_sync(0xFFFFFFFF, l0, off);
        l1 += __shfl_xor_sync(0xFFFFFFFF, l1, off);
    }
    float inv0 = 1.0f / l0, inv1 = 1.0f / l1;
    float* op0 = g_O + (size_t)qr0 * QDIM + h * HD + (size_t)g * QDIM;
    float* op1 = op0 + (size_t)8 * QDIM;
    #pragma unroll
    for (int j = 0; j < 8; j++) {
        *(float2*)&op0[j * 8 + 2 * t] = make_float2(o[j][0] * inv0, o[j][1] * inv0);
        *(float2*)&op1[j * 8 + 2 * t] = make_float2(o[j][2] * inv1, o[j][3] * inv1);
    }
}

// ---------------------------------------------------------------------------
// Launcher
// ---------------------------------------------------------------------------
extern "C" void kernel_launch(void* const* d_in, const int* in_sizes, int n_in,
                              void* d_out, int out_size)
{
    const float* x    = (const float*)d_in[0];
    const float* fcos = (const float*)d_in[1];
    const float* fsin = (const float*)d_in[2];
    const float* Wq   = (const float*)d_in[3];
    const float* Wk   = (const float*)d_in[4];
    const float* Wv   = (const float*)d_in[5];
    const float* Wo   = (const float*)d_in[6];
    float* out = (float*)d_out;

    static float *pQ = nullptr, *pK = nullptr, *pV = nullptr, *pO = nullptr;
    if (!pQ) {
        cudaGetSymbolAddress((void**)&pQ, g_Q);
        cudaGetSymbolAddress((void**)&pK, g_K);
        cudaGetSymbolAddress((void**)&pV, g_V);
        cudaGetSymbolAddress((void**)&pO, g_O);
    }

    // QKV projections (RoPE fused into Q and K epilogues)
    gemm_tf32<128, 128, 2, 4><<<dim3(QDIM / 128,  N_TOK / 128), 256>>>(
        x, Wq, pQ, N_TOK, QDIM,  D_MODEL, fcos, fsin);
    gemm_tf32<64, 64, 4, 2><<<dim3(KVDIM / 64, N_TOK / 64), 256>>>(
        x, Wk, pK, N_TOK, KVDIM, D_MODEL, fcos, fsin);
    gemm_tf32<64, 64, 4, 2><<<dim3(KVDIM / 64, N_TOK / 64), 256>>>(
        x, Wv, pV, N_TOK, KVDIM, D_MODEL, nullptr, nullptr);

    // Attention (KV tile shared across the 4 query heads of each KV head)
    attn_mma<<<dim3(N_TOK / 64, H_KV), 512>>>();

    // Output projection
    gemm_tf32<128, 128, 2, 4><<<dim3(D_MODEL / 128, N_TOK / 128), 256>>>(
        pO, Wo, out, N_TOK, D_MODEL, QDIM, nullptr, nullptr);
}

// round 4
// speedup vs baseline: 4.7338x; 1.0133x over previous
#include <cuda_runtime.h>
#include <math.h>
#include <stdint.h>

#define N_TOK   2048
#define D_MODEL 1024
#define H_Q     16
#define H_KV    4
#define HD      64
#define REPEATS (H_Q / H_KV)   // 4
#define QDIM    (H_Q * HD)     // 1024
#define KVDIM   (H_KV * HD)    // 256
#define SCALE   0.125f         // 1/sqrt(64)

// Scratch (allocation-free rule: __device__ globals)
__device__ float g_Q[N_TOK * QDIM];   // 8 MB
__device__ float g_K[N_TOK * KVDIM];  // 2 MB
__device__ float g_V[N_TOK * KVDIM];  // 2 MB
__device__ float g_O[N_TOK * QDIM];   // 8 MB

// ---------------------------------------------------------------------------
// tf32 helpers
// ---------------------------------------------------------------------------
__device__ __forceinline__ uint32_t f2tf32(float f) {
    uint32_t r;
    asm("cvt.rna.tf32.f32 %0, %1;" : "=r"(r) : "f"(f));
    return r;
}

__device__ __forceinline__ void mma_tf32(float* d, const uint32_t* a, const uint32_t* b) {
    asm volatile(
        "mma.sync.aligned.m16n8k8.row.col.f32.tf32.tf32.f32 "
        "{%0,%1,%2,%3}, {%4,%5,%6,%7}, {%8,%9}, {%0,%1,%2,%3};"
        : "+f"(d[0]), "+f"(d[1]), "+f"(d[2]), "+f"(d[3])
        : "r"(a[0]), "r"(a[1]), "r"(a[2]), "r"(a[3]),
          "r"(b[0]), "r"(b[1]));
}

#define LDA 36   // A smem [m][k] pad: frag bank = (4g+t) -> conflict-free
#define LDB 136  // B smem [k][n] pad: frag bank = (8t+g) -> conflict-free

// ---------------------------------------------------------------------------
// Shared GEMM body: 128x128x32 tile, 256 threads, warp grid 2x4 (warp 64x32),
// register-staged prefetch, optional fused RoPE (head-local pair index).
// ---------------------------------------------------------------------------
__device__ __forceinline__ void gemm_body_128(
    const float* __restrict__ A, const float* __restrict__ B,
    float* __restrict__ C, int K, int NcB, int rowBase, int colBase,
    const float* __restrict__ fcos, const float* __restrict__ fsin, bool rope,
    uint32_t* As, uint32_t* Bs)
{
    const int tid  = threadIdx.x;
    const int lane = tid & 31;
    const int w    = tid >> 5;
    const int g    = lane >> 2;
    const int t    = lane & 3;
    const int wm   = w >> 2;      // 0..1
    const int wn   = w & 3;       // 0..3

    float acc[4][4][4];
    #pragma unroll
    for (int mi = 0; mi < 4; mi++)
        #pragma unroll
        for (int nj = 0; nj < 4; nj++)
            #pragma unroll
            for (int r = 0; r < 4; r++) acc[mi][nj][r] = 0.0f;

    float4 aReg[4], bReg[4];
    #pragma unroll
    for (int p = 0; p < 4; p++) {
        int idx = tid + p * 256;
        int r = idx >> 3, c4 = (idx & 7) << 2;
        aReg[p] = *(const float4*)&A[(size_t)(rowBase + r) * K + c4];
    }
    #pragma unroll
    for (int p = 0; p < 4; p++) {
        int idx = tid + p * 256;
        int r = idx >> 5, c4 = (idx & 31) << 2;
        bReg[p] = *(const float4*)&B[(size_t)r * NcB + colBase + c4];
    }

    for (int k0 = 0; k0 < K; k0 += 32) {
        #pragma unroll
        for (int p = 0; p < 4; p++) {
            int idx = tid + p * 256;
            int r = idx >> 3, c4 = (idx & 7) << 2;
            *(uint4*)&As[r * LDA + c4] = make_uint4(
                f2tf32(aReg[p].x), f2tf32(aReg[p].y),
                f2tf32(aReg[p].z), f2tf32(aReg[p].w));
        }
        #pragma unroll
        for (int p = 0; p < 4; p++) {
            int idx = tid + p * 256;
            int r = idx >> 5, c4 = (idx & 31) << 2;
            *(uint4*)&Bs[r * LDB + c4] = make_uint4(
                f2tf32(bReg[p].x), f2tf32(bReg[p].y),
                f2tf32(bReg[p].z), f2tf32(bReg[p].w));
        }
        __syncthreads();

        if (k0 + 32 < K) {
            #pragma unroll
            for (int p = 0; p < 4; p++) {
                int idx = tid + p * 256;
                int r = idx >> 3, c4 = (idx & 7) << 2;
                aReg[p] = *(const float4*)&A[(size_t)(rowBase + r) * K + k0 + 32 + c4];
            }
            #pragma unroll
            for (int p = 0; p < 4; p++) {
                int idx = tid + p * 256;
                int r = idx >> 5, c4 = (idx & 31) << 2;
                bReg[p] = *(const float4*)&B[(size_t)(k0 + 32 + r) * NcB + colBase + c4];
            }
        }

        #pragma unroll
        for (int kk = 0; kk < 4; kk++) {
            const int kb = kk * 8;
            uint32_t af[4][4];
            #pragma unroll
            for (int mi = 0; mi < 4; mi++) {
                int mr = wm * 64 + mi * 16;
                af[mi][0] = As[(mr + g)     * LDA + kb + t];
                af[mi][1] = As[(mr + g + 8) * LDA + kb + t];
                af[mi][2] = As[(mr + g)     * LDA + kb + t + 4];
                af[mi][3] = As[(mr + g + 8) * LDA + kb + t + 4];
            }
            #pragma unroll
            for (int nj = 0; nj < 4; nj++) {
                int nc = wn * 32 + nj * 8;
                uint32_t bf[2];
                bf[0] = Bs[(kb + t)     * LDB + nc + g];
                bf[1] = Bs[(kb + t + 4) * LDB + nc + g];
                #pragma unroll
                for (int mi = 0; mi < 4; mi++)
                    mma_tf32(acc[mi][nj], af[mi], bf);
            }
        }
        __syncthreads();
    }

    #pragma unroll
    for (int mi = 0; mi < 4; mi++) {
        int row = rowBase + wm * 64 + mi * 16 + g;
        #pragma unroll
        for (int nj = 0; nj < 4; nj++) {
            int col = colBase + wn * 32 + nj * 8 + 2 * t;
            float v0 = acc[mi][nj][0], v1 = acc[mi][nj][1];
            float v2 = acc[mi][nj][2], v3 = acc[mi][nj][3];
            if (rope) {
                int i = (col & (HD - 1)) >> 1;
                float c0 = fcos[row * (HD / 2) + i];
                float s0 = fsin[row * (HD / 2) + i];
                float c1 = fcos[(row + 8) * (HD / 2) + i];
                float s1 = fsin[(row + 8) * (HD / 2) + i];
                float r0 = v0 * c0 - v1 * s0, i0 = v0 * s0 + v1 * c0;
                float r1 = v2 * c1 - v3 * s1, i1 = v2 * s1 + v3 * c1;
                v0 = r0; v1 = i0; v2 = r1; v3 = i1;
            }
            *(float2*)&C[(size_t)row * NcB + col]       = make_float2(v0, v1);
            *(float2*)&C[(size_t)(row + 8) * NcB + col] = make_float2(v2, v3);
        }
    }
}

// ---------------------------------------------------------------------------
// Fused QKV projection: grid (12, 16). bx<8 -> Q (rope), bx<10 -> K (rope),
// else V. One wave, RoPE fused.
// ---------------------------------------------------------------------------
__global__ __launch_bounds__(256, 2) void qkv_gemm(
    const float* __restrict__ x,
    const float* __restrict__ Wq, const float* __restrict__ Wk,
    const float* __restrict__ Wv,
    float* __restrict__ Q, float* __restrict__ Kp, float* __restrict__ Vp,
    const float* __restrict__ fcos, const float* __restrict__ fsin)
{
    __shared__ uint32_t As[128 * LDA];
    __shared__ uint32_t Bs[32 * LDB];

    const int bx = blockIdx.x;
    const float* B; float* C; int NcB; int colBase; bool rope;
    if (bx < 8)       { B = Wq; C = Q;  NcB = QDIM;  colBase = bx * 128;        rope = true;  }
    else if (bx < 10) { B = Wk; C = Kp; NcB = KVDIM; colBase = (bx - 8) * 128;  rope = true;  }
    else              { B = Wv; C = Vp; NcB = KVDIM; colBase = (bx - 10) * 128; rope = false; }

    gemm_body_128(x, B, C, D_MODEL, NcB, blockIdx.y * 128, colBase,
                  fcos, fsin, rope, As, Bs);
}

// Plain GEMM (output projection)
__global__ __launch_bounds__(256, 2) void gemm_out(
    const float* __restrict__ A, const float* __restrict__ B,
    float* __restrict__ C, int K, int NcB)
{
    __shared__ uint32_t As[128 * LDA];
    __shared__ uint32_t Bs[32 * LDB];
    gemm_body_128(A, B, C, K, NcB, blockIdx.y * 128, blockIdx.x * 128,
                  nullptr, nullptr, false, As, Bs);
}

// ---------------------------------------------------------------------------
// FlashAttention-2 tf32 mma attention.
// Grid (N_TOK/64, H_KV, 2), 256 threads (8 warps = 2 heads x 4 q-subtiles).
// K/V stored in smem in FRAGMENT ORDER: one uint2 per lane per 8x8 block ->
// every B-fragment is a single conflict-free LDS.64.
//   KF[(j*8+kf)*33 + lane] = { K[j*8+g][kf*8+t], K[j*8+g][kf*8+t+4] }
//   VF[(kb*8+j)*33 + lane] = { V[kb*8+t][j*8+g], V[kb*8+t+4][j*8+g] }
// with lane = g*4+t.
// ---------------------------------------------------------------------------
#define FS 33   // fragment-block stride in uint2 (pad for conflict-free STS)

__global__ __launch_bounds__(256, 2) void attn_mma()
{
    __shared__ uint2 KF[64 * FS];
    __shared__ uint2 VF[64 * FS];

    const int kvh = blockIdx.y;
    const int n0  = blockIdx.x * 64;
    const int tid = threadIdx.x;
    const int lane = tid & 31;
    const int w    = tid >> 5;
    const int g    = lane >> 2;
    const int t    = lane & 3;
    const int h    = kvh * REPEATS + blockIdx.z * 2 + (w >> 2);
    const int qr0  = n0 + (w & 3) * 16;

    // Q fragments, register-resident, pre-scaled, tf32
    uint32_t qf[8][4];
    {
        const float* q0 = g_Q + (size_t)qr0 * QDIM + h * HD;
        #pragma unroll
        for (int kf = 0; kf < 8; kf++) {
            qf[kf][0] = f2tf32(q0[(size_t)g       * QDIM + kf * 8 + t]     * SCALE);
            qf[kf][1] = f2tf32(q0[(size_t)(g + 8) * QDIM + kf * 8 + t]     * SCALE);
            qf[kf][2] = f2tf32(q0[(size_t)g       * QDIM + kf * 8 + t + 4] * SCALE);
            qf[kf][3] = f2tf32(q0[(size_t)(g + 8) * QDIM + kf * 8 + t + 4] * SCALE);
        }
    }

    float m0 = -INFINITY, m1 = -INFINITY, l0 = 0.0f, l1 = 0.0f;
    float o[8][4];
    #pragma unroll
    for (int j = 0; j < 8; j++)
        #pragma unroll
        for (int r = 0; r < 4; r++) o[j][r] = 0.0f;

    const int srcA = (lane & 28) | (t >> 1);
    const int srcB = srcA | 2;
    const bool oddT = (t & 1);

    uint32_t* KW = (uint32_t*)KF;
    uint32_t* VW = (uint32_t*)VF;

    for (int t0 = 0; t0 < N_TOK; t0 += 64) {
        __syncthreads();   // prior tile fully consumed
        // Load K,V tiles, converting to tf32 fragment order at store.
        #pragma unroll
        for (int p = 0; p < 4; p++) {
            int idx = tid + p * 256;           // 0..1023
            int rr = idx >> 4, c4 = (idx & 15) << 2;
            float4 kv = *(const float4*)&g_K[(size_t)(t0 + rr) * KVDIM + kvh * HD + c4];
            {
                int j = rr >> 3, gk = rr & 7;
                int kf = c4 >> 3, e = (c4 >> 2) & 1;
                int base = ((j * 8 + kf) * FS + gk * 4) * 2 + e;
                KW[base + 0] = f2tf32(kv.x);
                KW[base + 2] = f2tf32(kv.y);
                KW[base + 4] = f2tf32(kv.z);
                KW[base + 6] = f2tf32(kv.w);
            }
            float4 vv = *(const float4*)&g_V[(size_t)(t0 + rr) * KVDIM + kvh * HD + c4];
            {
                int kb = rr >> 3, tv = rr & 3, ev = (rr >> 2) & 1;
                int jv = c4 >> 3, gv = c4 & 7;
                int base = (kb * 8 + jv) * FS * 2 + tv * 2 + ev;
                VW[base + (gv + 0) * 8] = f2tf32(vv.x);
                VW[base + (gv + 1) * 8] = f2tf32(vv.y);
                VW[base + (gv + 2) * 8] = f2tf32(vv.z);
                VW[base + (gv + 3) * 8] = f2tf32(vv.w);
            }
        }
        __syncthreads();

        // S = (Q*scale) @ K^T : one LDS.64 per fragment
        float s[8][4];
        #pragma unroll
        for (int j = 0; j < 8; j++)
            #pragma unroll
            for (int r = 0; r < 4; r++) s[j][r] = 0.0f;
        #pragma unroll
        for (int kf = 0; kf < 8; kf++) {
            #pragma unroll
            for (int j = 0; j < 8; j++) {
                uint2 b = KF[(j * 8 + kf) * FS + lane];
                mma_tf32(s[j], qf[kf], &b.x);
            }
        }

        // Online softmax
        float tm0 = -INFINITY, tm1 = -INFINITY;
        #pragma unroll
        for (int j = 0; j < 8; j++) {
            tm0 = fmaxf(tm0, fmaxf(s[j][0], s[j][1]));
            tm1 = fmaxf(tm1, fmaxf(s[j][2], s[j][3]));
        }
        #pragma unroll
        for (int off = 1; off < 4; off <<= 1) {
            tm0 = fmaxf(tm0, __shfl_xor_sync(0xFFFFFFFF, tm0, off));
            tm1 = fmaxf(tm1, __shfl_xor_sync(0xFFFFFFFF, tm1, off));
        }
        float mn0 = fmaxf(m0, tm0), mn1 = fmaxf(m1, tm1);
        float c0 = __expf(m0 - mn0), c1 = __expf(m1 - mn1);
        l0 *= c0; l1 *= c1;
        #pragma unroll
        for (int j = 0; j < 8; j++) {
            o[j][0] *= c0; o[j][1] *= c0;
            o[j][2] *= c1; o[j][3] *= c1;
        }
        m0 = mn0; m1 = mn1;

        // Per 8-key block: exp, register shuffle-permute D-frag -> A-frag,
        // then O += P @ V (one LDS.64 per V fragment).
        #pragma unroll
        for (int kb = 0; kb < 8; kb++) {
            float p00 = __expf(s[kb][0] - mn0), p01 = __expf(s[kb][1] - mn0);
            float p10 = __expf(s[kb][2] - mn1), p11 = __expf(s[kb][3] - mn1);
            l0 += p00 + p01;
            l1 += p10 + p11;
            uint32_t u00 = f2tf32(p00), u01 = f2tf32(p01);
            uint32_t u10 = f2tf32(p10), u11 = f2tf32(p11);

            uint32_t pa[4], lo, hi;
            lo = __shfl_sync(0xFFFFFFFF, u00, srcA);
            hi = __shfl_sync(0xFFFFFFFF, u01, srcA);
            pa[0] = oddT ? hi : lo;                 // P(g, t)
            lo = __shfl_sync(0xFFFFFFFF, u00, srcB);
            hi = __shfl_sync(0xFFFFFFFF, u01, srcB);
            pa[2] = oddT ? hi : lo;                 // P(g, t+4)
            lo = __shfl_sync(0xFFFFFFFF, u10, srcA);
            hi = __shfl_sync(0xFFFFFFFF, u11, srcA);
            pa[1] = oddT ? hi : lo;                 // P(g+8, t)
            lo = __shfl_sync(0xFFFFFFFF, u10, srcB);
            hi = __shfl_sync(0xFFFFFFFF, u11, srcB);
            pa[3] = oddT ? hi : lo;                 // P(g+8, t+4)

            #pragma unroll
            for (int j = 0; j < 8; j++) {
                uint2 b = VF[(kb * 8 + j) * FS + lane];
                mma_tf32(o[j], pa, &b.x);
            }
        }
    }

    // Final normalize + write
    #pragma unroll
    for (int off = 1; off < 4; off <<= 1) {
        l0 += __shfl_xor_sync(0xFFFFFFFF, l0, off);
        l1 += __shfl_xor_sync(0xFFFFFFFF, l1, off);
    }
    float inv0 = 1.0f / l0, inv1 = 1.0f / l1;
    float* op0 = g_O + (size_t)qr0 * QDIM + h * HD + (size_t)g * QDIM;
    float* op1 = op0 + (size_t)8 * QDIM;
    #pragma unroll
    for (int j = 0; j < 8; j++) {
        *(float2*)&op0[j * 8 + 2 * t] = make_float2(o[j][0] * inv0, o[j][1] * inv0);
        *(float2*)&op1[j * 8 + 2 * t] = make_float2(o[j][2] * inv1, o[j][3] * inv1);
    }
}

// ---------------------------------------------------------------------------
// Launcher
// ---------------------------------------------------------------------------
extern "C" void kernel_launch(void* const* d_in, const int* in_sizes, int n_in,
                              void* d_out, int out_size)
{
    const float* x    = (const float*)d_in[0];
    const float* fcos = (const float*)d_in[1];
    const float* fsin = (const float*)d_in[2];
    const float* Wq   = (const float*)d_in[3];
    const float* Wk   = (const float*)d_in[4];
    const float* Wv   = (const float*)d_in[5];
    const float* Wo   = (const float*)d_in[6];
    float* out = (float*)d_out;

    static float *pQ = nullptr, *pK = nullptr, *pV = nullptr, *pO = nullptr;
    if (!pQ) {
        cudaGetSymbolAddress((void**)&pQ, g_Q);
        cudaGetSymbolAddress((void**)&pK, g_K);
        cudaGetSymbolAddress((void**)&pV, g_V);
        cudaGetSymbolAddress((void**)&pO, g_O);
    }

    // Fused QKV projection + RoPE (one wave: 192 blocks)
    qkv_gemm<<<dim3(12, N_TOK / 128), 256>>>(x, Wq, Wk, Wv, pQ, pK, pV, fcos, fsin);

    // Attention (2 heads per block, fragment-order smem)
    attn_mma<<<dim3(N_TOK / 64, H_KV, 2), 256>>>();

    // Output projection
    gemm_out<<<dim3(D_MODEL / 128, N_TOK / 128), 256>>>(pO, Wo, out, QDIM, D_MODEL);
}

// round 6
// speedup vs baseline: 5.9678x; 1.2607x over previous
#include <cuda_runtime.h>
#include <math.h>
#include <stdint.h>

#define N_TOK   2048
#define D_MODEL 1024
#define H_Q     16
#define H_KV    4
#define HD      64
#define REPEATS (H_Q / H_KV)   // 4
#define QDIM    (H_Q * HD)     // 1024
#define KVDIM   (H_KV * HD)    // 256
#define SCALE   0.125f         // 1/sqrt(64)

// tf32-bit scratch (allocation-free rule: __device__ globals)
__device__ uint32_t g_Xb [N_TOK * D_MODEL];
__device__ uint32_t g_Wqb[D_MODEL * QDIM];
__device__ uint32_t g_Wkb[D_MODEL * KVDIM];
__device__ uint32_t g_Wvb[D_MODEL * KVDIM];
__device__ uint32_t g_Wob[QDIM * D_MODEL];
__device__ uint32_t g_Qb [N_TOK * QDIM];    // RoPE'd, pre-scaled tf32 bits
__device__ uint32_t g_KFb[N_TOK * KVDIM];   // K, mma-B-fragment order
__device__ uint32_t g_VFb[N_TOK * KVDIM];   // V, mma-B-fragment order
__device__ uint32_t g_Ob [N_TOK * QDIM];    // attention out, tf32 bits

// ---------------------------------------------------------------------------
// helpers
// ---------------------------------------------------------------------------
__device__ __forceinline__ uint32_t f2tf32(float f) {
    uint32_t r;
    asm("cvt.rna.tf32.f32 %0, %1;" : "=r"(r) : "f"(f));
    return r;
}

__device__ __forceinline__ void mma_tf32(float* d, const uint32_t* a, const uint32_t* b) {
    asm volatile(
        "mma.sync.aligned.m16n8k8.row.col.f32.tf32.tf32.f32 "
        "{%0,%1,%2,%3}, {%4,%5,%6,%7}, {%8,%9}, {%0,%1,%2,%3};"
        : "+f"(d[0]), "+f"(d[1]), "+f"(d[2]), "+f"(d[3])
        : "r"(a[0]), "r"(a[1]), "r"(a[2]), "r"(a[3]),
          "r"(b[0]), "r"(b[1]));
}

__device__ __forceinline__ void cp16(void* smem_dst, const void* gsrc) {
    uint32_t s = (uint32_t)__cvta_generic_to_shared(smem_dst);
    asm volatile("cp.async.cg.shared.global [%0], [%1], 16;" :: "r"(s), "l"(gsrc));
}
#define CP_COMMIT() asm volatile("cp.async.commit_group;")
#define CP_WAIT0()  asm volatile("cp.async.wait_group 0;")

// Fragment-order scatter stores for K/V (layout consumed by attn_mma):
//   KF block (j*8+kf): lane g*4+t holds {K[j8+g][kf8+t], K[j8+g][kf8+t+4]}
//   VF block (kb*8+j): lane g*4+t holds {V[kb8+t][j8+g], V[kb8+t+4][j8+g]}
__device__ __forceinline__ void storeK(int kvh, int token, int dcol, uint32_t bits) {
    int tile = token >> 6, j = (token & 63) >> 3, gq = token & 7;
    int kf = dcol >> 3, tt = dcol & 7;
    size_t idx = ((size_t)((kvh * 32 + tile) * 64 + j * 8 + kf)) * 64
               + (gq * 4 + (tt & 3)) * 2 + (tt >> 2);
    g_KFb[idx] = bits;
}
__device__ __forceinline__ void storeV(int kvh, int token, int dcol, uint32_t bits) {
    int tile = token >> 6, kb = (token & 63) >> 3, tt = token & 7;
    int j = dcol >> 3, gq = dcol & 7;
    size_t idx = ((size_t)((kvh * 32 + tile) * 64 + kb * 8 + j)) * 64
               + (gq * 4 + (tt & 3)) * 2 + (tt >> 2);
    g_VFb[idx] = bits;
}

// ---------------------------------------------------------------------------
// One-shot fp32 -> tf32-bit conversion of x and all weights (fused).
// ---------------------------------------------------------------------------
#define C_X  (N_TOK * D_MODEL / 4)          // 524288
#define C_WQ (D_MODEL * QDIM / 4)           // 262144
#define C_WK (D_MODEL * KVDIM / 4)          // 65536
#define C_WV (D_MODEL * KVDIM / 4)          // 65536
#define C_WO (QDIM * D_MODEL / 4)           // 262144
#define C_TOT (C_X + C_WQ + C_WK + C_WV + C_WO)

__global__ void cvt_all(const float4* __restrict__ x,
                        const float4* __restrict__ Wq, const float4* __restrict__ Wk,
                        const float4* __restrict__ Wv, const float4* __restrict__ Wo)
{
    for (int i = blockIdx.x * blockDim.x + threadIdx.x; i < C_TOT;
         i += gridDim.x * blockDim.x) {
        const float4* src; uint32_t* dst; int off = i;
        if (off < C_X)                 { src = x;  dst = g_Xb; }
        else if ((off -= C_X)  < C_WQ) { src = Wq; dst = g_Wqb; }
        else if ((off -= C_WQ) < C_WK) { src = Wk; dst = g_Wkb; }
        else if ((off -= C_WK) < C_WV) { src = Wv; dst = g_Wvb; }
        else    { off -= C_WV;           src = Wo; dst = g_Wob; }
        float4 v = src[off];
        *(uint4*)&dst[(size_t)off * 4] =
            make_uint4(f2tf32(v.x), f2tf32(v.y), f2tf32(v.z), f2tf32(v.w));
    }
}

// ---------------------------------------------------------------------------
// cp.async double-buffered tf32 GEMM body: 128x128x32, 256 thr, warps 2x4.
// A,B are tf32-bit uint32 arrays. Epilogue functor gets (row,col,v0..v3)
// where (row,col),(row,col+1),(row+8,col),(row+8,col+1).
// ---------------------------------------------------------------------------
#define LDA 36
#define LDB 136
#define GEMM_SMEM ((2 * (128 * LDA + 32 * LDB)) * 4)

template<typename Epi>
__device__ __forceinline__ void gemm_body_cp(
    const uint32_t* __restrict__ A, const uint32_t* __restrict__ B,
    int K, int NcB, int rowBase, int colBase, uint32_t* smem, Epi&& epi)
{
    uint32_t* As = smem;                    // 2 x 128*LDA
    uint32_t* Bs = smem + 2 * 128 * LDA;    // 2 x 32*LDB

    const int tid  = threadIdx.x;
    const int lane = tid & 31;
    const int w    = tid >> 5;
    const int g    = lane >> 2;
    const int t    = lane & 3;
    const int wm   = w >> 2;
    const int wn   = w & 3;

    float acc[4][4][4];
    #pragma unroll
    for (int mi = 0; mi < 4; mi++)
        #pragma unroll
        for (int nj = 0; nj < 4; nj++)
            #pragma unroll
            for (int r = 0; r < 4; r++) acc[mi][nj][r] = 0.0f;

    auto issue = [&](int k0, int stg) {
        uint32_t* a = As + stg * 128 * LDA;
        uint32_t* b = Bs + stg * 32 * LDB;
        #pragma unroll
        for (int p = 0; p < 4; p++) {
            int idx = tid + p * 256;
            int r = idx >> 3, c4 = (idx & 7) << 2;
            cp16(&a[r * LDA + c4], &A[(size_t)(rowBase + r) * K + k0 + c4]);
        }
        #pragma unroll
        for (int p = 0; p < 4; p++) {
            int idx = tid + p * 256;
            int r = idx >> 5, c4 = (idx & 31) << 2;
            cp16(&b[r * LDB + c4], &B[(size_t)(k0 + r) * NcB + colBase + c4]);
        }
        CP_COMMIT();
    };

    issue(0, 0);
    int stg = 0;
    for (int k0 = 0; k0 < K; k0 += 32) {
        CP_WAIT0();
        __syncthreads();
        if (k0 + 32 < K) issue(k0 + 32, stg ^ 1);

        const uint32_t* a = As + stg * 128 * LDA;
        const uint32_t* b = Bs + stg * 32 * LDB;
        #pragma unroll
        for (int kk = 0; kk < 4; kk++) {
            const int kb = kk * 8;
            uint32_t af[4][4];
            #pragma unroll
            for (int mi = 0; mi < 4; mi++) {
                int mr = wm * 64 + mi * 16;
                af[mi][0] = a[(mr + g)     * LDA + kb + t];
                af[mi][1] = a[(mr + g + 8) * LDA + kb + t];
                af[mi][2] = a[(mr + g)     * LDA + kb + t + 4];
                af[mi][3] = a[(mr + g + 8) * LDA + kb + t + 4];
            }
            #pragma unroll
            for (int nj = 0; nj < 4; nj++) {
                int nc = wn * 32 + nj * 8;
                uint32_t bf[2];
                bf[0] = b[(kb + t)     * LDB + nc + g];
                bf[1] = b[(kb + t + 4) * LDB + nc + g];
                #pragma unroll
                for (int mi = 0; mi < 4; mi++)
                    mma_tf32(acc[mi][nj], af[mi], bf);
            }
        }
        stg ^= 1;
    }

    #pragma unroll
    for (int mi = 0; mi < 4; mi++) {
        int row = rowBase + wm * 64 + mi * 16 + g;
        #pragma unroll
        for (int nj = 0; nj < 4; nj++) {
            int col = colBase + wn * 32 + nj * 8 + 2 * t;
            epi(row, col, acc[mi][nj][0], acc[mi][nj][1],
                          acc[mi][nj][2], acc[mi][nj][3]);
        }
    }
}

// ---------------------------------------------------------------------------
// Fused QKV projection. grid (12, 16): bx<8 Q, bx<10 K, else V.
// Q: RoPE + prescale -> g_Qb.  K: RoPE -> g_KFb frag order.  V -> g_VFb.
// (Lambdas declared inside __global__ code are implicitly device lambdas.)
// ---------------------------------------------------------------------------
__global__ __launch_bounds__(256, 2) void qkv_gemm(
    const float* __restrict__ fcos, const float* __restrict__ fsin)
{
    extern __shared__ uint32_t smem[];
    const int bx = blockIdx.x;
    const int rowBase = blockIdx.y * 128;

    if (bx < 8) {
        const int colBase = bx * 128;
        gemm_body_cp(g_Xb, g_Wqb, D_MODEL, QDIM, rowBase, colBase, smem,
            [&](int row, int col, float v0, float v1, float v2, float v3) {
                int i = (col & (HD - 1)) >> 1;
                float c0 = fcos[row * 32 + i],       s0 = fsin[row * 32 + i];
                float c1 = fcos[(row + 8) * 32 + i], s1 = fsin[(row + 8) * 32 + i];
                float r0 = v0 * c0 - v1 * s0, i0 = v0 * s0 + v1 * c0;
                float r1 = v2 * c1 - v3 * s1, i1 = v2 * s1 + v3 * c1;
                *(uint2*)&g_Qb[(size_t)row * QDIM + col] =
                    make_uint2(f2tf32(r0 * SCALE), f2tf32(i0 * SCALE));
                *(uint2*)&g_Qb[(size_t)(row + 8) * QDIM + col] =
                    make_uint2(f2tf32(r1 * SCALE), f2tf32(i1 * SCALE));
            });
    } else if (bx < 10) {
        const int colBase = (bx - 8) * 128;
        gemm_body_cp(g_Xb, g_Wkb, D_MODEL, KVDIM, rowBase, colBase, smem,
            [&](int row, int col, float v0, float v1, float v2, float v3) {
                int kvh = col >> 6, dcol = col & 63;
                int i = dcol >> 1;
                float c0 = fcos[row * 32 + i],       s0 = fsin[row * 32 + i];
                float c1 = fcos[(row + 8) * 32 + i], s1 = fsin[(row + 8) * 32 + i];
                float r0 = v0 * c0 - v1 * s0, i0 = v0 * s0 + v1 * c0;
                float r1 = v2 * c1 - v3 * s1, i1 = v2 * s1 + v3 * c1;
                storeK(kvh, row,     dcol,     f2tf32(r0));
                storeK(kvh, row,     dcol + 1, f2tf32(i0));
                storeK(kvh, row + 8, dcol,     f2tf32(r1));
                storeK(kvh, row + 8, dcol + 1, f2tf32(i1));
            });
    } else {
        const int colBase = (bx - 10) * 128;
        gemm_body_cp(g_Xb, g_Wvb, D_MODEL, KVDIM, rowBase, colBase, smem,
            [&](int row, int col, float v0, float v1, float v2, float v3) {
                int kvh = col >> 6, dcol = col & 63;
                storeV(kvh, row,     dcol,     f2tf32(v0));
                storeV(kvh, row,     dcol + 1, f2tf32(v1));
                storeV(kvh, row + 8, dcol,     f2tf32(v2));
                storeV(kvh, row + 8, dcol + 1, f2tf32(v3));
            });
    }
}

// Output projection: out = g_Ob @ g_Wob, fp32 result.
__global__ __launch_bounds__(256, 2) void gemm_out(float* __restrict__ out)
{
    extern __shared__ uint32_t smem[];
    gemm_body_cp(g_Ob, g_Wob, QDIM, D_MODEL, blockIdx.y * 128, blockIdx.x * 128, smem,
        [&](int row, int col, float v0, float v1, float v2, float v3) {
            *(float2*)&out[(size_t)row * D_MODEL + col]       = make_float2(v0, v1);
            *(float2*)&out[(size_t)(row + 8) * D_MODEL + col] = make_float2(v2, v3);
        });
}

// ---------------------------------------------------------------------------
// FlashAttention-2, tf32 mma, cp.async double-buffered fragment tiles.
// grid (N_TOK/64, H_KV, 2), 256 threads (8 warps = 2 heads x 4 q-subtiles).
// ---------------------------------------------------------------------------
#define ATTN_SMEM (2 * 8192 * 4)   // 2 stages x (K 4096 + V 4096) u32

__global__ __launch_bounds__(256, 2) void attn_mma()
{
    extern __shared__ uint32_t sm[];

    const int kvh = blockIdx.y;
    const int tid = threadIdx.x;
    const int lane = tid & 31;
    const int w    = tid >> 5;
    const int g    = lane >> 2;
    const int t    = lane & 3;
    const int h    = kvh * REPEATS + blockIdx.z * 2 + (w >> 2);
    const int n0   = blockIdx.x * 64;
    const int qr0  = n0 + (w & 3) * 16;
    const int tile0 = blockIdx.x;   // start at own tile index (spreads L2)

    // Q fragments (already RoPE'd, scaled, tf32 bits)
    uint32_t qf[8][4];
    {
        const uint32_t* q0 = g_Qb + (size_t)qr0 * QDIM + h * HD;
        #pragma unroll
        for (int kf = 0; kf < 8; kf++) {
            qf[kf][0] = q0[(size_t)g       * QDIM + kf * 8 + t];
            qf[kf][1] = q0[(size_t)(g + 8) * QDIM + kf * 8 + t];
            qf[kf][2] = q0[(size_t)g       * QDIM + kf * 8 + t + 4];
            qf[kf][3] = q0[(size_t)(g + 8) * QDIM + kf * 8 + t + 4];
        }
    }

    float m0 = -INFINITY, m1 = -INFINITY, l0 = 0.0f, l1 = 0.0f;
    float o[8][4];
    #pragma unroll
    for (int j = 0; j < 8; j++)
        #pragma unroll
        for (int r = 0; r < 4; r++) o[j][r] = 0.0f;

    const int srcA = (lane & 28) | (t >> 1);
    const int srcB = srcA | 2;
    const bool oddT = (t & 1);

    auto issue = [&](int tile, int stg) {
        const uint32_t* ks = g_KFb + (size_t)(kvh * 32 + tile) * 4096;
        const uint32_t* vs = g_VFb + (size_t)(kvh * 32 + tile) * 4096;
        uint32_t* dK = sm + stg * 8192;
        uint32_t* dV = dK + 4096;
        #pragma unroll
        for (int p = 0; p < 4; p++) {
            int idx = (tid + p * 256) * 4;
            cp16(&dK[idx], &ks[idx]);
            cp16(&dV[idx], &vs[idx]);
        }
        CP_COMMIT();
    };

    issue(tile0, 0);
    int stg = 0;
    for (int it = 0; it < N_TOK / 64; it++) {
        CP_WAIT0();
        __syncthreads();
        if (it + 1 < N_TOK / 64) issue((tile0 + it + 1) & 31, stg ^ 1);

        const uint2* KFs = (const uint2*)(sm + stg * 8192);
        const uint2* VFs = (const uint2*)(sm + stg * 8192 + 4096);

        // S = Q @ K^T
        float s[8][4];
        #pragma unroll
        for (int j = 0; j < 8; j++)
            #pragma unroll
            for (int r = 0; r < 4; r++) s[j][r] = 0.0f;
        #pragma unroll
        for (int kf = 0; kf < 8; kf++) {
            #pragma unroll
            for (int j = 0; j < 8; j++) {
                uint2 b = KFs[(j * 8 + kf) * 32 + lane];
                mma_tf32(s[j], qf[kf], &b.x);
            }
        }

        // Online softmax
        float tm0 = -INFINITY, tm1 = -INFINITY;
        #pragma unroll
        for (int j = 0; j < 8; j++) {
            tm0 = fmaxf(tm0, fmaxf(s[j][0], s[j][1]));
            tm1 = fmaxf(tm1, fmaxf(s[j][2], s[j][3]));
        }
        #pragma unroll
        for (int off = 1; off < 4; off <<= 1) {
            tm0 = fmaxf(tm0, __shfl_xor_sync(0xFFFFFFFF, tm0, off));
            tm1 = fmaxf(tm1, __shfl_xor_sync(0xFFFFFFFF, tm1, off));
        }
        float mn0 = fmaxf(m0, tm0), mn1 = fmaxf(m1, tm1);
        float c0 = __expf(m0 - mn0), c1 = __expf(m1 - mn1);
        l0 *= c0; l1 *= c1;
        #pragma unroll
        for (int j = 0; j < 8; j++) {
            o[j][0] *= c0; o[j][1] *= c0;
            o[j][2] *= c1; o[j][3] *= c1;
        }
        m0 = mn0; m1 = mn1;

        // exp + register permute (D-frag -> A-frag) + O += P @ V
        #pragma unroll
        for (int kb = 0; kb < 8; kb++) {
            float p00 = __expf(s[kb][0] - mn0), p01 = __expf(s[kb][1] - mn0);
            float p10 = __expf(s[kb][2] - mn1), p11 = __expf(s[kb][3] - mn1);
            l0 += p00 + p01;
            l1 += p10 + p11;
            uint32_t u00 = f2tf32(p00), u01 = f2tf32(p01);
            uint32_t u10 = f2tf32(p10), u11 = f2tf32(p11);

            uint32_t pa[4], lo, hi;
            lo = __shfl_sync(0xFFFFFFFF, u00, srcA);
            hi = __shfl_sync(0xFFFFFFFF, u01, srcA);
            pa[0] = oddT ? hi : lo;
            lo = __shfl_sync(0xFFFFFFFF, u00, srcB);
            hi = __shfl_sync(0xFFFFFFFF, u01, srcB);
            pa[2] = oddT ? hi : lo;
            lo = __shfl_sync(0xFFFFFFFF, u10, srcA);
            hi = __shfl_sync(0xFFFFFFFF, u11, srcA);
            pa[1] = oddT ? hi : lo;
            lo = __shfl_sync(0xFFFFFFFF, u10, srcB);
            hi = __shfl_sync(0xFFFFFFFF, u11, srcB);
            pa[3] = oddT ? hi : lo;

            #pragma unroll
            for (int j = 0; j < 8; j++) {
                uint2 b = VFs[(kb * 8 + j) * 32 + lane];
                mma_tf32(o[j], pa, &b.x);
            }
        }
        stg ^= 1;
    }

    // Normalize + write tf32 bits (consumed by gemm_out)
    #pragma unroll
    for (int off = 1; off < 4; off <<= 1) {
        l0 += __shfl_xor_sync(0xFFFFFFFF, l0, off);
        l1 += __shfl_xor_sync(0xFFFFFFFF, l1, off);
    }
    float inv0 = 1.0f / l0, inv1 = 1.0f / l1;
    uint32_t* op0 = g_Ob + (size_t)(qr0 + g) * QDIM + h * HD;
    uint32_t* op1 = op0 + (size_t)8 * QDIM;
    #pragma unroll
    for (int j = 0; j < 8; j++) {
        *(uint2*)&op0[j * 8 + 2 * t] =
            make_uint2(f2tf32(o[j][0] * inv0), f2tf32(o[j][1] * inv0));
        *(uint2*)&op1[j * 8 + 2 * t] =
            make_uint2(f2tf32(o[j][2] * inv1), f2tf32(o[j][3] * inv1));
    }
}

// ---------------------------------------------------------------------------
// Launcher
// ---------------------------------------------------------------------------
extern "C" void kernel_launch(void* const* d_in, const int* in_sizes, int n_in,
                              void* d_out, int out_size)
{
    const float* x    = (const float*)d_in[0];
    const float* fcos = (const float*)d_in[1];
    const float* fsin = (const float*)d_in[2];
    const float* Wq   = (const float*)d_in[3];
    const float* Wk   = (const float*)d_in[4];
    const float* Wv   = (const float*)d_in[5];
    const float* Wo   = (const float*)d_in[6];
    float* out = (float*)d_out;

    static bool init = false;
    if (!init) {
        cudaFuncSetAttribute(qkv_gemm, cudaFuncAttributeMaxDynamicSharedMemorySize, GEMM_SMEM);
        cudaFuncSetAttribute(gemm_out, cudaFuncAttributeMaxDynamicSharedMemorySize, GEMM_SMEM);
        cudaFuncSetAttribute(attn_mma, cudaFuncAttributeMaxDynamicSharedMemorySize, ATTN_SMEM);
        init = true;
    }

    // 1. fp32 -> tf32 bits (x + all weights)
    cvt_all<<<2048, 256>>>((const float4*)x, (const float4*)Wq, (const float4*)Wk,
                           (const float4*)Wv, (const float4*)Wo);

    // 2. Fused QKV projection + RoPE, K/V written in fragment order
    qkv_gemm<<<dim3(12, N_TOK / 128), 256, GEMM_SMEM>>>(fcos, fsin);

    // 3. Attention
    attn_mma<<<dim3(N_TOK / 64, H_KV, 2), 256, ATTN_SMEM>>>();

    // 4. Output projection
    gemm_out<<<dim3(D_MODEL / 128, N_TOK / 128), 256, GEMM_SMEM>>>(out);
}

// round 9
// speedup vs baseline: 7.5839x; 1.2708x over previous
#include <cuda_runtime.h>
#include <math.h>
#include <stdint.h>

#define N_TOK   2048
#define D_MODEL 1024
#define H_Q     16
#define H_KV    4
#define HD      64
#define REPEATS (H_Q / H_KV)   // 4
#define QDIM    (H_Q * HD)     // 1024
#define KVDIM   (H_KV * HD)    // 256
#define QSCALE  0.1803368801111244f   // (1/sqrt(64)) * log2(e)

// scratch (allocation-free rule: __device__ globals)
// A-frag layout: [rowTile128][kTile32] blobs of 4096 u32;
//   blob: [mb(8)][kb(4)][lane(32) uint4 = {(g,t),(g+8,t),(g,t+4),(g+8,t+4)}]
// B-frag layout: [colTile128][kTile32] blobs of 4096 u32;
//   blob: [nb(16)][kb(4)][lane(32) uint2 = {(k t, n g),(k t+4, n g)}]
__device__ uint32_t g_Xf [N_TOK * D_MODEL];    // x, A-frag
__device__ uint32_t g_WqF[D_MODEL * QDIM];     // B-frag
__device__ uint32_t g_WkF[D_MODEL * KVDIM];
__device__ uint32_t g_WvF[D_MODEL * KVDIM];
__device__ uint32_t g_WoF[QDIM * D_MODEL];
__device__ uint32_t g_Qb [N_TOK * QDIM];       // Q row-major, RoPE'd, *QSCALE, tf32
__device__ uint32_t g_KFb[N_TOK * KVDIM];      // K tf32, S-mma B-frag order
__device__ uint32_t g_VFh[N_TOK * KVDIM / 2];  // V fp16x2, PV-mma B-frag order
__device__ uint32_t g_Of [N_TOK * QDIM];       // attention out, A-frag

// ---------------------------------------------------------------------------
// helpers
// ---------------------------------------------------------------------------
__device__ __forceinline__ uint32_t f2tf32(float f) {
    uint32_t r;
    asm("cvt.rna.tf32.f32 %0, %1;" : "=r"(r) : "f"(f));
    return r;
}
__device__ __forceinline__ uint16_t f2fp16(float f) {
    uint16_t r;
    asm("cvt.rn.f16.f32 %0, %1;" : "=h"(r) : "f"(f));
    return r;
}
__device__ __forceinline__ uint32_t packh2(float lo, float hi) {
    uint32_t r;
    asm("cvt.rn.f16x2.f32 %0, %1, %2;" : "=r"(r) : "f"(hi), "f"(lo));
    return r;
}
__device__ __forceinline__ float ex2f(float x) {
    float r;
    asm("ex2.approx.ftz.f32 %0, %1;" : "=f"(r) : "f"(x));
    return r;
}
__device__ __forceinline__ void mma_tf32(float* d, const uint32_t* a, const uint32_t* b) {
    asm volatile(
        "mma.sync.aligned.m16n8k8.row.col.f32.tf32.tf32.f32 "
        "{%0,%1,%2,%3}, {%4,%5,%6,%7}, {%8,%9}, {%0,%1,%2,%3};"
        : "+f"(d[0]), "+f"(d[1]), "+f"(d[2]), "+f"(d[3])
        : "r"(a[0]), "r"(a[1]), "r"(a[2]), "r"(a[3]), "r"(b[0]), "r"(b[1]));
}
__device__ __forceinline__ void mma_f16(float* d, uint32_t a0, uint32_t a1,
                                        uint32_t a2, uint32_t a3,
                                        uint32_t b0, uint32_t b1) {
    asm volatile(
        "mma.sync.aligned.m16n8k16.row.col.f32.f16.f16.f32 "
        "{%0,%1,%2,%3}, {%4,%5,%6,%7}, {%8,%9}, {%0,%1,%2,%3};"
        : "+f"(d[0]), "+f"(d[1]), "+f"(d[2]), "+f"(d[3])
        : "r"(a0), "r"(a1), "r"(a2), "r"(a3), "r"(b0), "r"(b1));
}
__device__ __forceinline__ void cp16(void* smem_dst, const void* gsrc) {
    uint32_t s = (uint32_t)__cvta_generic_to_shared(smem_dst);
    asm volatile("cp.async.cg.shared.global [%0], [%1], 16;" :: "r"(s), "l"(gsrc));
}
#define CP_COMMIT() asm volatile("cp.async.commit_group;")
#define CP_WAIT0()  asm volatile("cp.async.wait_group 0;")

// ---------------------------------------------------------------------------
// Prep: x -> A-frag tf32; weights -> B-frag tf32 (transposed on the fly)
// ---------------------------------------------------------------------------
__global__ void prep_x(const float* __restrict__ x) {
    const int total = N_TOK * D_MODEL / 4;   // uint4 count
    for (int u = blockIdx.x * blockDim.x + threadIdx.x; u < total;
         u += gridDim.x * blockDim.x) {
        int tile = u >> 10, w = u & 1023;
        int blk = w >> 5, l = w & 31;
        int rt = tile >> 5, kt = tile & 31;
        int mb = blk >> 2, kb = blk & 3;
        int g = l >> 2, t = l & 3;
        int r0 = rt * 128 + mb * 16 + g;
        int c0 = kt * 32 + kb * 8 + t;
        uint4 v;
        v.x = f2tf32(x[(size_t)r0 * D_MODEL + c0]);
        v.y = f2tf32(x[(size_t)(r0 + 8) * D_MODEL + c0]);
        v.z = f2tf32(x[(size_t)r0 * D_MODEL + c0 + 4]);
        v.w = f2tf32(x[(size_t)(r0 + 8) * D_MODEL + c0 + 4]);
        ((uint4*)g_Xf)[u] = v;
    }
}

__global__ void prep_w(const float* __restrict__ Wq, const float* __restrict__ Wk,
                       const float* __restrict__ Wv, const float* __restrict__ Wo)
{
    const int CQ = 524288, CK = 131072, CV = 131072, CO = 524288;  // uint2 counts
    const int total = CQ + CK + CV + CO;
    for (int u = blockIdx.x * blockDim.x + threadIdx.x; u < total;
         u += gridDim.x * blockDim.x) {
        const float* W; uint32_t* dst; int Nc; int off = u;
        if (off < CQ)                 { W = Wq; dst = g_WqF; Nc = QDIM; }
        else if ((off -= CQ) < CK)    { W = Wk; dst = g_WkF; Nc = KVDIM; }
        else if ((off -= CK) < CV)    { W = Wv; dst = g_WvF; Nc = KVDIM; }
        else    { off -= CV;            W = Wo; dst = g_WoF; Nc = D_MODEL; }
        int tile = off >> 11, w = off & 2047;
        int blk = w >> 5, l = w & 31;
        int ct = tile >> 5, kt = tile & 31;
        int nb = blk >> 2, kb = blk & 3;
        int g = l >> 2, t = l & 3;
        int k0 = kt * 32 + kb * 8 + t;
        int n  = ct * 128 + nb * 8 + g;
        uint2 v;
        v.x = f2tf32(W[(size_t)k0 * Nc + n]);
        v.y = f2tf32(W[(size_t)(k0 + 4) * Nc + n]);
        ((uint2*)dst)[off] = v;
    }
}

// Fragment-order scatter stores (consumed by attention)
__device__ __forceinline__ void storeK(int kvh, int token, int dcol, uint32_t bits) {
    int tile = token >> 6, j = (token & 63) >> 3, gq = token & 7;
    int kf = dcol >> 3, tt = dcol & 7;
    size_t idx = ((size_t)((kvh * 32 + tile) * 64 + j * 8 + kf)) * 64
               + (gq * 4 + (tt & 3)) * 2 + (tt >> 2);
    g_KFb[idx] = bits;
}
__device__ __forceinline__ void storeV16(int kvh, int token, int dcol, uint16_t b) {
    int tile = token >> 6, kin = token & 63;
    int kbl = kin >> 4, kk = kin & 15;
    int half = kk >> 3, tt = (kk >> 1) & 3, e = kk & 1;
    int j = dcol >> 3, gg = dcol & 7;
    size_t word = ((size_t)(kvh * 32 + tile)) * 2048
                + ((kbl * 8 + j) * 32 + (gg * 4 + tt)) * 2 + half;
    ((uint16_t*)g_VFh)[word * 2 + e] = b;
}

// ---------------------------------------------------------------------------
// Fragment-layout tf32 GEMM: 128x128 tile, 256 thr, warps 2x4 (64x32 each),
// A/B in frag-order global blobs, cp.async double-buffered. K = nkt*32.
// ---------------------------------------------------------------------------
#define GEMM_SMEM 65536

template<typename Epi>
__device__ __forceinline__ void gemm_frag(
    const uint32_t* __restrict__ A, const uint32_t* __restrict__ B,
    int rt, int ct, int nkt, char* smem, Epi&& epi)
{
    const int tid = threadIdx.x, lane = tid & 31, w = tid >> 5;
    const int wm = w >> 2, wn = w & 3, g = lane >> 2, t = lane & 3;
    uint32_t* sm32 = (uint32_t*)smem;

    float acc[4][4][4];
    #pragma unroll
    for (int mi = 0; mi < 4; mi++)
        #pragma unroll
        for (int nj = 0; nj < 4; nj++)
            #pragma unroll
            for (int r = 0; r < 4; r++) acc[mi][nj][r] = 0.0f;

    auto issue = [&](int kt, int bb) {
        const uint4* a4 = (const uint4*)(A + ((size_t)rt * nkt + kt) * 4096);
        const uint4* b4 = (const uint4*)(B + ((size_t)ct * nkt + kt) * 4096);
        uint32_t* dA = sm32 + bb * 8192;
        uint32_t* dB = dA + 4096;
        #pragma unroll
        for (int p = 0; p < 4; p++) {
            int i = tid + p * 256;
            cp16(&dA[i * 4], &a4[i]);
            cp16(&dB[i * 4], &b4[i]);
        }
        CP_COMMIT();
    };

    issue(0, 0);
    int stg = 0;
    for (int it = 0; it < nkt; it++) {
        CP_WAIT0();
        __syncthreads();
        if (it + 1 < nkt) issue(it + 1, stg ^ 1);

        const uint4* As4 = (const uint4*)(sm32 + stg * 8192);
        const uint2* Bs2 = (const uint2*)(sm32 + stg * 8192 + 4096);
        #pragma unroll
        for (int kb = 0; kb < 4; kb++) {
            uint4 af[4]; uint2 bf[4];
            #pragma unroll
            for (int mi = 0; mi < 4; mi++)
                af[mi] = As4[((wm * 4 + mi) * 4 + kb) * 32 + lane];
            #pragma unroll
            for (int nj = 0; nj < 4; nj++)
                bf[nj] = Bs2[((wn * 4 + nj) * 4 + kb) * 32 + lane];
            #pragma unroll
            for (int mi = 0; mi < 4; mi++)
                #pragma unroll
                for (int nj = 0; nj < 4; nj++)
                    mma_tf32(acc[mi][nj], (const uint32_t*)&af[mi],
                             (const uint32_t*)&bf[nj]);
        }
        stg ^= 1;
    }

    #pragma unroll
    for (int mi = 0; mi < 4; mi++) {
        int row = rt * 128 + wm * 64 + mi * 16 + g;
        #pragma unroll
        for (int nj = 0; nj < 4; nj++) {
            int col = ct * 128 + wn * 32 + nj * 8 + 2 * t;
            epi(row, col, acc[mi][nj][0], acc[mi][nj][1],
                          acc[mi][nj][2], acc[mi][nj][3]);
        }
    }
}

// ---------------------------------------------------------------------------
// Fused QKV projection. grid (12, 16): bx<8 Q, bx<10 K, else V.
// ---------------------------------------------------------------------------
__global__ __launch_bounds__(256, 2) void qkv_gemm(
    const float* __restrict__ fcos, const float* __restrict__ fsin)
{
    extern __shared__ char smem[];
    const int bx = blockIdx.x, rt = blockIdx.y;

    if (bx < 8) {
        gemm_frag(g_Xf, g_WqF, rt, bx, 32, smem,
            [&](int row, int col, float v0, float v1, float v2, float v3) {
                int i = (col & 63) >> 1;
                float c0 = fcos[row * 32 + i],       s0 = fsin[row * 32 + i];
                float c1 = fcos[(row + 8) * 32 + i], s1 = fsin[(row + 8) * 32 + i];
                *(uint2*)&g_Qb[(size_t)row * QDIM + col] = make_uint2(
                    f2tf32((v0 * c0 - v1 * s0) * QSCALE),
                    f2tf32((v0 * s0 + v1 * c0) * QSCALE));
                *(uint2*)&g_Qb[(size_t)(row + 8) * QDIM + col] = make_uint2(
                    f2tf32((v2 * c1 - v3 * s1) * QSCALE),
                    f2tf32((v2 * s1 + v3 * c1) * QSCALE));
            });
    } else if (bx < 10) {
        gemm_frag(g_Xf, g_WkF, rt, bx - 8, 32, smem,
            [&](int row, int col, float v0, float v1, float v2, float v3) {
                int kvh = col >> 6, dcol = col & 63;
                int i = dcol >> 1;
                float c0 = fcos[row * 32 + i],       s0 = fsin[row * 32 + i];
                float c1 = fcos[(row + 8) * 32 + i], s1 = fsin[(row + 8) * 32 + i];
                storeK(kvh, row,     dcol,     f2tf32(v0 * c0 - v1 * s0));
                storeK(kvh, row,     dcol + 1, f2tf32(v0 * s0 + v1 * c0));
                storeK(kvh, row + 8, dcol,     f2tf32(v2 * c1 - v3 * s1));
                storeK(kvh, row + 8, dcol + 1, f2tf32(v2 * s1 + v3 * c1));
            });
    } else {
        gemm_frag(g_Xf, g_WvF, rt, bx - 10, 32, smem,
            [&](int row, int col, float v0, float v1, float v2, float v3) {
                int kvh = col >> 6, dcol = col & 63;
                storeV16(kvh, row,     dcol,     f2fp16(v0));
                storeV16(kvh, row,     dcol + 1, f2fp16(v1));
                storeV16(kvh, row + 8, dcol,     f2fp16(v2));
                storeV16(kvh, row + 8, dcol + 1, f2fp16(v3));
            });
    }
}

// Output projection: out = g_Of @ WoF, fp32 result.
__global__ __launch_bounds__(256, 2) void gemm_out(float* __restrict__ out)
{
    extern __shared__ char smem[];
    gemm_frag(g_Of, g_WoF, blockIdx.y, blockIdx.x, 32, smem,
        [&](int row, int col, float v0, float v1, float v2, float v3) {
            *(float2*)&out[(size_t)row * D_MODEL + col]       = make_float2(v0, v1);
            *(float2*)&out[(size_t)(row + 8) * D_MODEL + col] = make_float2(v2, v3);
        });
}

// ---------------------------------------------------------------------------
// FlashAttention-2: S in tf32 mma (K frag smem), softmax in base-2,
// P packed fp16 per-thread (no shuffles), PV in fp16 m16n8k16.
// grid (32, H_KV, 2), 256 threads (8 warps = 2 heads x 4 q-subtiles).
// ---------------------------------------------------------------------------
#define ATTN_SMEM (2 * 6144 * 4)   // 2 stages x (K 16KB + V 8KB)

__global__ __launch_bounds__(256, 2) void attn_mma()
{
    extern __shared__ uint32_t sm[];

    const int kvh = blockIdx.y;
    const int tid = threadIdx.x;
    const int lane = tid & 31;
    const int w    = tid >> 5;
    const int g    = lane >> 2;
    const int t    = lane & 3;
    const int h    = kvh * REPEATS + blockIdx.z * 2 + (w >> 2);
    const int qr0  = blockIdx.x * 64 + (w & 3) * 16;
    const int tile0 = blockIdx.x;

    // Q fragments (RoPE'd, *QSCALE, tf32 bits)
    uint32_t qf[8][4];
    {
        const uint32_t* q0 = g_Qb + (size_t)qr0 * QDIM + h * HD;
        #pragma unroll
        for (int kf = 0; kf < 8; kf++) {
            qf[kf][0] = q0[(size_t)g       * QDIM + kf * 8 + t];
            qf[kf][1] = q0[(size_t)(g + 8) * QDIM + kf * 8 + t];
            qf[kf][2] = q0[(size_t)g       * QDIM + kf * 8 + t + 4];
            qf[kf][3] = q0[(size_t)(g + 8) * QDIM + kf * 8 + t + 4];
        }
    }

    float m0 = -INFINITY, m1 = -INFINITY, l0 = 0.0f, l1 = 0.0f;
    float o[8][4];
    #pragma unroll
    for (int j = 0; j < 8; j++)
        #pragma unroll
        for (int r = 0; r < 4; r++) o[j][r] = 0.0f;

    auto issue = [&](int tile, int stg) {
        const uint4* ks = (const uint4*)(g_KFb + (size_t)(kvh * 32 + tile) * 4096);
        const uint4* vs = (const uint4*)(g_VFh + (size_t)(kvh * 32 + tile) * 2048);
        uint32_t* dK = sm + stg * 6144;
        uint32_t* dV = dK + 4096;
        #pragma unroll
        for (int p = 0; p < 4; p++)
            cp16(&dK[(tid + p * 256) * 4], &ks[tid + p * 256]);
        #pragma unroll
        for (int p = 0; p < 2; p++)
            cp16(&dV[(tid + p * 256) * 4], &vs[tid + p * 256]);
        CP_COMMIT();
    };

    issue(tile0, 0);
    int stg = 0;
    for (int it = 0; it < 32; it++) {
        CP_WAIT0();
        __syncthreads();
        if (it + 1 < 32) issue((tile0 + it + 1) & 31, stg ^ 1);

        const uint2* KFs = (const uint2*)(sm + stg * 6144);
        const uint2* VFs = (const uint2*)(sm + stg * 6144 + 4096);

        // S = Q @ K^T (scores already in log2 units)
        float s[8][4];
        #pragma unroll
        for (int j = 0; j < 8; j++)
            #pragma unroll
            for (int r = 0; r < 4; r++) s[j][r] = 0.0f;
        #pragma unroll
        for (int kf = 0; kf < 8; kf++) {
            #pragma unroll
            for (int j = 0; j < 8; j++) {
                uint2 b = KFs[(j * 8 + kf) * 32 + lane];
                mma_tf32(s[j], qf[kf], &b.x);
            }
        }

        // Online softmax, base-2
        float tm0 = -INFINITY, tm1 = -INFINITY;
        #pragma unroll
        for (int j = 0; j < 8; j++) {
            tm0 = fmaxf(tm0, fmaxf(s[j][0], s[j][1]));
            tm1 = fmaxf(tm1, fmaxf(s[j][2], s[j][3]));
        }
        #pragma unroll
        for (int off = 1; off < 4; off <<= 1) {
            tm0 = fmaxf(tm0, __shfl_xor_sync(0xFFFFFFFF, tm0, off));
            tm1 = fmaxf(tm1, __shfl_xor_sync(0xFFFFFFFF, tm1, off));
        }
        float mn0 = fmaxf(m0, tm0), mn1 = fmaxf(m1, tm1);
        float c0 = ex2f(m0 - mn0), c1 = ex2f(m1 - mn1);
        l0 *= c0; l1 *= c1;
        #pragma unroll
        for (int j = 0; j < 8; j++) {
            o[j][0] *= c0; o[j][1] *= c0;
            o[j][2] *= c1; o[j][3] *= c1;
        }
        m0 = mn0; m1 = mn1;

        // P = 2^(s-m), packed fp16 per-thread (D-frag == f16 A-frag layout),
        // then O += P @ V with m16n8k16 f16.
        #pragma unroll
        for (int kbl = 0; kbl < 4; kbl++) {
            float pa0 = ex2f(s[2 * kbl][0] - mn0),     pa1 = ex2f(s[2 * kbl][1] - mn0);
            float pa2 = ex2f(s[2 * kbl][2] - mn1),     pa3 = ex2f(s[2 * kbl][3] - mn1);
            float pb0 = ex2f(s[2 * kbl + 1][0] - mn0), pb1 = ex2f(s[2 * kbl + 1][1] - mn0);
            float pb2 = ex2f(s[2 * kbl + 1][2] - mn1), pb3 = ex2f(s[2 * kbl + 1][3] - mn1);
            l0 += pa0 + pa1 + pb0 + pb1;
            l1 += pa2 + pa3 + pb2 + pb3;
            uint32_t a0 = packh2(pa0, pa1);   // rows g,   k 0..7 of block
            uint32_t a1 = packh2(pa2, pa3);   // rows g+8, k 0..7
            uint32_t a2 = packh2(pb0, pb1);   // rows g,   k 8..15
            uint32_t a3 = packh2(pb2, pb3);   // rows g+8, k 8..15
            #pragma unroll
            for (int j = 0; j < 8; j++) {
                uint2 vv = VFs[(kbl * 8 + j) * 32 + lane];
                mma_f16(o[j], a0, a1, a2, a3, vv.x, vv.y);
            }
        }
        stg ^= 1;
    }

    // Normalize, permute D-frag -> A-frag, store g_Of (A-frag blobs)
    #pragma unroll
    for (int off = 1; off < 4; off <<= 1) {
        l0 += __shfl_xor_sync(0xFFFFFFFF, l0, off);
        l1 += __shfl_xor_sync(0xFFFFFFFF, l1, off);
    }
    float inv0 = 1.0f / l0, inv1 = 1.0f / l1;
    const int srcA = (lane & 28) | (t >> 1);
    const int srcB = srcA | 2;
    const bool oddT = (t & 1);
    const int rt = qr0 >> 7;
    const int mb = (qr0 >> 4) & 7;
    uint4* of4 = (uint4*)g_Of;
    #pragma unroll
    for (int j = 0; j < 8; j++) {
        uint32_t u0 = f2tf32(o[j][0] * inv0), u1 = f2tf32(o[j][1] * inv0);
        uint32_t u2 = f2tf32(o[j][2] * inv1), u3 = f2tf32(o[j][3] * inv1);
        uint32_t lo, hi; uint4 a;
        lo = __shfl_sync(0xFFFFFFFF, u0, srcA);
        hi = __shfl_sync(0xFFFFFFFF, u1, srcA);
        a.x = oddT ? hi : lo;                       // (g, t)
        lo = __shfl_sync(0xFFFFFFFF, u2, srcA);
        hi = __shfl_sync(0xFFFFFFFF, u3, srcA);
        a.y = oddT ? hi : lo;                       // (g+8, t)
        lo = __shfl_sync(0xFFFFFFFF, u0, srcB);
        hi = __shfl_sync(0xFFFFFFFF, u1, srcB);
        a.z = oddT ? hi : lo;                       // (g, t+4)
        lo = __shfl_sync(0xFFFFFFFF, u2, srcB);
        hi = __shfl_sync(0xFFFFFFFF, u3, srcB);
        a.w = oddT ? hi : lo;                       // (g+8, t+4)
        int kt = h * 2 + (j >> 2), kb = j & 3;
        of4[((size_t)(rt * 32 + kt)) * 1024 + (mb * 4 + kb) * 32 + lane] = a;
    }
}

// ---------------------------------------------------------------------------
// Launcher
// ---------------------------------------------------------------------------
extern "C" void kernel_launch(void* const* d_in, const int* in_sizes, int n_in,
                              void* d_out, int out_size)
{
    const float* x    = (const float*)d_in[0];
    const float* fcos = (const float*)d_in[1];
    const float* fsin = (const float*)d_in[2];
    const float* Wq   = (const float*)d_in[3];
    const float* Wk   = (const float*)d_in[4];
    const float* Wv   = (const float*)d_in[5];
    const float* Wo   = (const float*)d_in[6];
    float* out = (float*)d_out;

    static bool init = false;
    if (!init) {
        cudaFuncSetAttribute(qkv_gemm, cudaFuncAttributeMaxDynamicSharedMemorySize, GEMM_SMEM);
        cudaFuncSetAttribute(gemm_out, cudaFuncAttributeMaxDynamicSharedMemorySize, GEMM_SMEM);
        cudaFuncSetAttribute(attn_mma, cudaFuncAttributeMaxDynamicSharedMemorySize, ATTN_SMEM);
        init = true;
    }

    // 1. prep: x -> A-frag tf32; weights -> B-frag tf32
    prep_x<<<2048, 256>>>(x);
    prep_w<<<2048, 256>>>(Wq, Wk, Wv, Wo);

    // 2. QKV projection + RoPE (frag-layout GEMM)
    qkv_gemm<<<dim3(12, N_TOK / 128), 256, GEMM_SMEM>>>(fcos, fsin);

    // 3. Attention (tf32 S, fp16 PV)
    attn_mma<<<dim3(N_TOK / 64, H_KV, 2), 256, ATTN_SMEM>>>();

    // 4. Output projection
    gemm_out<<<dim3(D_MODEL / 128, N_TOK / 128), 256, GEMM_SMEM>>>(out);
}

// round 10
// speedup vs baseline: 11.2692x; 1.4859x over previous
#include <cuda_runtime.h>
#include <math.h>
#include <stdint.h>

#define N_TOK   2048
#define D_MODEL 1024
#define H_Q     16
#define H_KV    4
#define HD      64
#define REPEATS (H_Q / H_KV)   // 4
#define QDIM    (H_Q * HD)     // 1024
#define KVDIM   (H_KV * HD)    // 256
#define QSCALE  0.1803368801111244f   // (1/sqrt(64)) * log2(e)

// scratch (allocation-free rule: __device__ globals), all fp16x2 words
// A-frag blob per [rowTile128][kTile32]: 512 uint4 = [mb(8)][kb(2)][lane(32)]
//   uint4 = {A[g,2t..],A[g+8,2t..],A[g,2t+8..],A[g+8,2t+8..]} (fp16 pairs)
// B-frag blob per [colTile128][kTile32]: 1024 uint2 = [nb(16)][kb(2)][lane(32)]
//   uint2 = {B[2t..,g], B[2t+8..,g]}
__device__ uint32_t g_Xf [N_TOK * D_MODEL / 2];
__device__ uint32_t g_WqF[D_MODEL * QDIM / 2];
__device__ uint32_t g_WkF[D_MODEL * KVDIM / 2];
__device__ uint32_t g_WvF[D_MODEL * KVDIM / 2];
__device__ uint32_t g_WoF[QDIM * D_MODEL / 2];
__device__ uint32_t g_Qh [N_TOK * QDIM / 2];    // Q row-major fp16, RoPE'd, *QSCALE
__device__ uint32_t g_KFb[N_TOK * KVDIM / 2];   // K fp16, S-mma B-frag order
__device__ uint32_t g_VFh[N_TOK * KVDIM / 2];   // V fp16, PV-mma B-frag order
__device__ uint32_t g_Of [N_TOK * QDIM / 2];    // attention out, fp16 A-frag

// ---------------------------------------------------------------------------
// helpers
// ---------------------------------------------------------------------------
__device__ __forceinline__ uint16_t f2fp16(float f) {
    uint16_t r;
    asm("cvt.rn.f16.f32 %0, %1;" : "=h"(r) : "f"(f));
    return r;
}
__device__ __forceinline__ uint32_t packh2(float lo, float hi) {
    uint32_t r;
    asm("cvt.rn.f16x2.f32 %0, %1, %2;" : "=r"(r) : "f"(hi), "f"(lo));
    return r;
}
__device__ __forceinline__ float ex2f(float x) {
    float r;
    asm("ex2.approx.ftz.f32 %0, %1;" : "=f"(r) : "f"(x));
    return r;
}
__device__ __forceinline__ void mma_f16(float* d, uint32_t a0, uint32_t a1,
                                        uint32_t a2, uint32_t a3,
                                        uint32_t b0, uint32_t b1) {
    asm volatile(
        "mma.sync.aligned.m16n8k16.row.col.f32.f16.f16.f32 "
        "{%0,%1,%2,%3}, {%4,%5,%6,%7}, {%8,%9}, {%0,%1,%2,%3};"
        : "+f"(d[0]), "+f"(d[1]), "+f"(d[2]), "+f"(d[3])
        : "r"(a0), "r"(a1), "r"(a2), "r"(a3), "r"(b0), "r"(b1));
}
__device__ __forceinline__ void cp16(void* smem_dst, const void* gsrc) {
    uint32_t s = (uint32_t)__cvta_generic_to_shared(smem_dst);
    asm volatile("cp.async.cg.shared.global [%0], [%1], 16;" :: "r"(s), "l"(gsrc));
}
#define CP_COMMIT() asm volatile("cp.async.commit_group;")
#define CP_WAIT0()  asm volatile("cp.async.wait_group 0;")

// ---------------------------------------------------------------------------
// Prep: x -> fp16 A-frag blobs; weights -> fp16 B-frag blobs
// ---------------------------------------------------------------------------
__global__ void prep_x(const float* __restrict__ x) {
    const int total = N_TOK * D_MODEL / 8;   // uint4 count
    for (int u = blockIdx.x * blockDim.x + threadIdx.x; u < total;
         u += gridDim.x * blockDim.x) {
        int blob = u >> 9, widx = u & 511;
        int rt = blob >> 5, kt = blob & 31;
        int mb = widx >> 6, kb = (widx >> 5) & 1, lane = widx & 31;
        int g = lane >> 2, t = lane & 3;
        int r0 = rt * 128 + mb * 16 + g;
        int c0 = kt * 32 + kb * 16 + 2 * t;
        const float* xr0 = x + (size_t)r0 * D_MODEL;
        const float* xr8 = xr0 + (size_t)8 * D_MODEL;
        uint4 v;
        v.x = packh2(xr0[c0],     xr0[c0 + 1]);
        v.y = packh2(xr8[c0],     xr8[c0 + 1]);
        v.z = packh2(xr0[c0 + 8], xr0[c0 + 9]);
        v.w = packh2(xr8[c0 + 8], xr8[c0 + 9]);
        ((uint4*)g_Xf)[u] = v;
    }
}

__global__ void prep_w(const float* __restrict__ Wq, const float* __restrict__ Wk,
                       const float* __restrict__ Wv, const float* __restrict__ Wo)
{
    const int CQ = 262144, CK = 65536, CV = 65536, CO = 262144;  // uint2 counts
    const int total = CQ + CK + CV + CO;
    for (int u = blockIdx.x * blockDim.x + threadIdx.x; u < total;
         u += gridDim.x * blockDim.x) {
        const float* W; uint32_t* dst; int Nc; int off = u;
        if (off < CQ)              { W = Wq; dst = g_WqF; Nc = QDIM; }
        else if ((off -= CQ) < CK) { W = Wk; dst = g_WkF; Nc = KVDIM; }
        else if ((off -= CK) < CV) { W = Wv; dst = g_WvF; Nc = KVDIM; }
        else { off -= CV;            W = Wo; dst = g_WoF; Nc = D_MODEL; }
        int blob = off >> 10, widx = off & 1023;
        int ct = blob >> 5, kt = blob & 31;
        int nb = widx >> 6, kb = (widx >> 5) & 1, lane = widx & 31;
        int g = lane >> 2, t = lane & 3;
        int k0 = kt * 32 + kb * 16 + 2 * t;
        int n  = ct * 128 + nb * 8 + g;
        uint2 v;
        v.x = packh2(W[(size_t)k0 * Nc + n],       W[(size_t)(k0 + 1) * Nc + n]);
        v.y = packh2(W[(size_t)(k0 + 8) * Nc + n], W[(size_t)(k0 + 9) * Nc + n]);
        ((uint2*)dst)[off] = v;
    }
}

// Fragment-order scatter stores (consumed by attention)
// K blob per [kvh*32+tile]: [j(8)][kf(4)][lane(32)] uint2 {b0,b1}
__device__ __forceinline__ void storeK2(int kvh, int token, int dcol,
                                        float v0, float v1) {
    int tile = token >> 6, j = (token & 63) >> 3, gq = token & 7;
    int kf = dcol >> 4, r = dcol & 15;
    int e = r >> 3, tt = (r & 7) >> 1;
    size_t idx = ((size_t)((kvh * 32 + tile) * 32 + j * 4 + kf)) * 64
               + (gq * 4 + tt) * 2 + e;
    g_KFb[idx] = packh2(v0, v1);
}
__device__ __forceinline__ void storeV16(int kvh, int token, int dcol, uint16_t b) {
    int tile = token >> 6, kin = token & 63;
    int kbl = kin >> 4, kk = kin & 15;
    int half = kk >> 3, tt = (kk >> 1) & 3, e = kk & 1;
    int j = dcol >> 3, gg = dcol & 7;
    size_t word = ((size_t)(kvh * 32 + tile)) * 2048
                + ((kbl * 8 + j) * 32 + (gg * 4 + tt)) * 2 + half;
    ((uint16_t*)g_VFh)[word * 2 + e] = b;
}

// ---------------------------------------------------------------------------
// fp16 frag-layout GEMM: 128x128 tile, 256 thr, warps 2x4 (64x32 each),
// cp.async double-buffered. K = nkt*32.
// ---------------------------------------------------------------------------
#define GEMM_SMEM 32768

template<typename Epi>
__device__ __forceinline__ void gemm_frag(
    const uint32_t* __restrict__ A, const uint32_t* __restrict__ B,
    int rt, int ct, int nkt, char* smem, Epi&& epi)
{
    const int tid = threadIdx.x, lane = tid & 31, w = tid >> 5;
    const int wm = w >> 2, wn = w & 3, g = lane >> 2, t = lane & 3;
    uint32_t* sm32 = (uint32_t*)smem;

    float acc[4][4][4];
    #pragma unroll
    for (int mi = 0; mi < 4; mi++)
        #pragma unroll
        for (int nj = 0; nj < 4; nj++)
            #pragma unroll
            for (int r = 0; r < 4; r++) acc[mi][nj][r] = 0.0f;

    auto issue = [&](int kt, int bb) {
        const uint4* a4 = (const uint4*)(A + ((size_t)rt * nkt + kt) * 2048);
        const uint4* b4 = (const uint4*)(B + ((size_t)ct * nkt + kt) * 2048);
        uint32_t* dA = sm32 + bb * 4096;
        uint32_t* dB = dA + 2048;
        #pragma unroll
        for (int p = 0; p < 2; p++) {
            int i = tid + p * 256;
            cp16(&dA[i * 4], &a4[i]);
            cp16(&dB[i * 4], &b4[i]);
        }
        CP_COMMIT();
    };

    issue(0, 0);
    int stg = 0;
    for (int it = 0; it < nkt; it++) {
        CP_WAIT0();
        __syncthreads();
        if (it + 1 < nkt) issue(it + 1, stg ^ 1);

        const uint4* As4 = (const uint4*)(sm32 + stg * 4096);
        const uint2* Bs2 = (const uint2*)(sm32 + stg * 4096 + 2048);
        #pragma unroll
        for (int kb = 0; kb < 2; kb++) {
            uint4 af[4]; uint2 bf[4];
            #pragma unroll
            for (int mi = 0; mi < 4; mi++)
                af[mi] = As4[((wm * 4 + mi) * 2 + kb) * 32 + lane];
            #pragma unroll
            for (int nj = 0; nj < 4; nj++)
                bf[nj] = Bs2[((wn * 4 + nj) * 2 + kb) * 32 + lane];
            #pragma unroll
            for (int mi = 0; mi < 4; mi++)
                #pragma unroll
                for (int nj = 0; nj < 4; nj++)
                    mma_f16(acc[mi][nj], af[mi].x, af[mi].y, af[mi].z, af[mi].w,
                            bf[nj].x, bf[nj].y);
        }
        stg ^= 1;
    }

    #pragma unroll
    for (int mi = 0; mi < 4; mi++) {
        int row = rt * 128 + wm * 64 + mi * 16 + g;
        #pragma unroll
        for (int nj = 0; nj < 4; nj++) {
            int col = ct * 128 + wn * 32 + nj * 8 + 2 * t;
            epi(row, col, acc[mi][nj][0], acc[mi][nj][1],
                          acc[mi][nj][2], acc[mi][nj][3]);
        }
    }
}

// ---------------------------------------------------------------------------
// Fused QKV projection. grid (12, 16): bx<8 Q, bx<10 K, else V.
// ---------------------------------------------------------------------------
__global__ __launch_bounds__(256, 2) void qkv_gemm(
    const float* __restrict__ fcos, const float* __restrict__ fsin)
{
    extern __shared__ char smem[];
    const int bx = blockIdx.x, rt = blockIdx.y;

    if (bx < 8) {
        gemm_frag(g_Xf, g_WqF, rt, bx, 32, smem,
            [&](int row, int col, float v0, float v1, float v2, float v3) {
                int i = (col & 63) >> 1;
                float c0 = fcos[row * 32 + i],       s0 = fsin[row * 32 + i];
                float c1 = fcos[(row + 8) * 32 + i], s1 = fsin[(row + 8) * 32 + i];
                g_Qh[(size_t)row * 512 + (col >> 1)] = packh2(
                    (v0 * c0 - v1 * s0) * QSCALE, (v0 * s0 + v1 * c0) * QSCALE);
                g_Qh[(size_t)(row + 8) * 512 + (col >> 1)] = packh2(
                    (v2 * c1 - v3 * s1) * QSCALE, (v2 * s1 + v3 * c1) * QSCALE);
            });
    } else if (bx < 10) {
        gemm_frag(g_Xf, g_WkF, rt, bx - 8, 32, smem,
            [&](int row, int col, float v0, float v1, float v2, float v3) {
                int kvh = col >> 6, dcol = col & 63;
                int i = dcol >> 1;
                float c0 = fcos[row * 32 + i],       s0 = fsin[row * 32 + i];
                float c1 = fcos[(row + 8) * 32 + i], s1 = fsin[(row + 8) * 32 + i];
                storeK2(kvh, row,     dcol, v0 * c0 - v1 * s0, v0 * s0 + v1 * c0);
                storeK2(kvh, row + 8, dcol, v2 * c1 - v3 * s1, v2 * s1 + v3 * c1);
            });
    } else {
        gemm_frag(g_Xf, g_WvF, rt, bx - 10, 32, smem,
            [&](int row, int col, float v0, float v1, float v2, float v3) {
                int kvh = col >> 6, dcol = col & 63;
                storeV16(kvh, row,     dcol,     f2fp16(v0));
                storeV16(kvh, row,     dcol + 1, f2fp16(v1));
                storeV16(kvh, row + 8, dcol,     f2fp16(v2));
                storeV16(kvh, row + 8, dcol + 1, f2fp16(v3));
            });
    }
}

// Output projection: out = g_Of @ WoF, fp32 result.
__global__ __launch_bounds__(256, 2) void gemm_out(float* __restrict__ out)
{
    extern __shared__ char smem[];
    gemm_frag(g_Of, g_WoF, blockIdx.y, blockIdx.x, 32, smem,
        [&](int row, int col, float v0, float v1, float v2, float v3) {
            *(float2*)&out[(size_t)row * D_MODEL + col]       = make_float2(v0, v1);
            *(float2*)&out[(size_t)(row + 8) * D_MODEL + col] = make_float2(v2, v3);
        });
}

// ---------------------------------------------------------------------------
// FlashAttention-2, all-fp16 MMAs, base-2 softmax, zero shuffles.
// grid (32, H_KV, 2), 256 threads (8 warps = 2 heads x 4 q-subtiles).
// ---------------------------------------------------------------------------
#define ATTN_SMEM (2 * 4096 * 4)   // 2 stages x (K 8KB + V 8KB)

__global__ __launch_bounds__(256, 2) void attn_mma()
{
    extern __shared__ uint32_t sm[];

    const int kvh = blockIdx.y;
    const int tid = threadIdx.x;
    const int lane = tid & 31;
    const int w    = tid >> 5;
    const int g    = lane >> 2;
    const int t    = lane & 3;
    const int h    = kvh * REPEATS + blockIdx.z * 2 + (w >> 2);
    const int qr0  = blockIdx.x * 64 + (w & 3) * 16;
    const int tile0 = blockIdx.x;

    // Q fragments (fp16 pairs; RoPE'd, *QSCALE)
    uint32_t qf[4][4];
    {
        const uint32_t* q0 = g_Qh + (size_t)qr0 * 512 + h * 32;
        #pragma unroll
        for (int kf = 0; kf < 4; kf++) {
            qf[kf][0] = q0[(size_t)g       * 512 + kf * 8 + t];
            qf[kf][1] = q0[(size_t)(g + 8) * 512 + kf * 8 + t];
            qf[kf][2] = q0[(size_t)g       * 512 + kf * 8 + t + 4];
            qf[kf][3] = q0[(size_t)(g + 8) * 512 + kf * 8 + t + 4];
        }
    }

    float m0 = -INFINITY, m1 = -INFINITY, l0 = 0.0f, l1 = 0.0f;
    float o[8][4];
    #pragma unroll
    for (int j = 0; j < 8; j++)
        #pragma unroll
        for (int r = 0; r < 4; r++) o[j][r] = 0.0f;

    auto issue = [&](int tile, int stg) {
        const uint4* ks = (const uint4*)(g_KFb + (size_t)(kvh * 32 + tile) * 2048);
        const uint4* vs = (const uint4*)(g_VFh + (size_t)(kvh * 32 + tile) * 2048);
        uint32_t* dK = sm + stg * 4096;
        uint32_t* dV = dK + 2048;
        #pragma unroll
        for (int p = 0; p < 2; p++) {
            int i = tid + p * 256;
            cp16(&dK[i * 4], &ks[i]);
            cp16(&dV[i * 4], &vs[i]);
        }
        CP_COMMIT();
    };

    issue(tile0, 0);
    int stg = 0;
    for (int it = 0; it < 32; it++) {
        CP_WAIT0();
        __syncthreads();
        if (it + 1 < 32) issue((tile0 + it + 1) & 31, stg ^ 1);

        const uint2* KFs = (const uint2*)(sm + stg * 4096);
        const uint2* VFs = (const uint2*)(sm + stg * 4096 + 2048);

        // S = Q @ K^T (log2 units)
        float s[8][4];
        #pragma unroll
        for (int j = 0; j < 8; j++)
            #pragma unroll
            for (int r = 0; r < 4; r++) s[j][r] = 0.0f;
        #pragma unroll
        for (int kf = 0; kf < 4; kf++) {
            #pragma unroll
            for (int j = 0; j < 8; j++) {
                uint2 b = KFs[(j * 4 + kf) * 32 + lane];
                mma_f16(s[j], qf[kf][0], qf[kf][1], qf[kf][2], qf[kf][3], b.x, b.y);
            }
        }

        // Online softmax, base-2
        float tm0 = -INFINITY, tm1 = -INFINITY;
        #pragma unroll
        for (int j = 0; j < 8; j++) {
            tm0 = fmaxf(tm0, fmaxf(s[j][0], s[j][1]));
            tm1 = fmaxf(tm1, fmaxf(s[j][2], s[j][3]));
        }
        #pragma unroll
        for (int off = 1; off < 4; off <<= 1) {
            tm0 = fmaxf(tm0, __shfl_xor_sync(0xFFFFFFFF, tm0, off));
            tm1 = fmaxf(tm1, __shfl_xor_sync(0xFFFFFFFF, tm1, off));
        }
        float mn0 = fmaxf(m0, tm0), mn1 = fmaxf(m1, tm1);
        float c0 = ex2f(m0 - mn0), c1 = ex2f(m1 - mn1);
        l0 *= c0; l1 *= c1;
        #pragma unroll
        for (int j = 0; j < 8; j++) {
            o[j][0] *= c0; o[j][1] *= c0;
            o[j][2] *= c1; o[j][3] *= c1;
        }
        m0 = mn0; m1 = mn1;

        // P = 2^(s-m) packed fp16 (D-frag == A-frag pairing), O += P @ V
        #pragma unroll
        for (int kbl = 0; kbl < 4; kbl++) {
            float pa0 = ex2f(s[2 * kbl][0] - mn0),     pa1 = ex2f(s[2 * kbl][1] - mn0);
            float pa2 = ex2f(s[2 * kbl][2] - mn1),     pa3 = ex2f(s[2 * kbl][3] - mn1);
            float pb0 = ex2f(s[2 * kbl + 1][0] - mn0), pb1 = ex2f(s[2 * kbl + 1][1] - mn0);
            float pb2 = ex2f(s[2 * kbl + 1][2] - mn1), pb3 = ex2f(s[2 * kbl + 1][3] - mn1);
            l0 += pa0 + pa1 + pb0 + pb1;
            l1 += pa2 + pa3 + pb2 + pb3;
            uint32_t a0 = packh2(pa0, pa1);
            uint32_t a1 = packh2(pa2, pa3);
            uint32_t a2 = packh2(pb0, pb1);
            uint32_t a3 = packh2(pb2, pb3);
            #pragma unroll
            for (int j = 0; j < 8; j++) {
                uint2 vv = VFs[(kbl * 8 + j) * 32 + lane];
                mma_f16(o[j], a0, a1, a2, a3, vv.x, vv.y);
            }
        }
        stg ^= 1;
    }

    // Normalize + store as fp16 A-frag (no shuffles: D-pairs == A-pairs)
    #pragma unroll
    for (int off = 1; off < 4; off <<= 1) {
        l0 += __shfl_xor_sync(0xFFFFFFFF, l0, off);
        l1 += __shfl_xor_sync(0xFFFFFFFF, l1, off);
    }
    float inv0 = 1.0f / l0, inv1 = 1.0f / l1;
    const int rt = qr0 >> 7;
    const int mb = (qr0 >> 4) & 7;
    uint4* of4 = (uint4*)g_Of;
    #pragma unroll
    for (int jp = 0; jp < 4; jp++) {
        int j0 = 2 * jp, j1 = j0 + 1;
        uint4 a;
        a.x = packh2(o[j0][0] * inv0, o[j0][1] * inv0);   // row g,   k 0..7
        a.y = packh2(o[j0][2] * inv1, o[j0][3] * inv1);   // row g+8, k 0..7
        a.z = packh2(o[j1][0] * inv0, o[j1][1] * inv0);   // row g,   k 8..15
        a.w = packh2(o[j1][2] * inv1, o[j1][3] * inv1);   // row g+8, k 8..15
        int kt = h * 2 + (jp >> 1), kb = jp & 1;
        of4[((size_t)(rt * 32 + kt)) * 512 + (mb * 2 + kb) * 32 + lane] = a;
    }
}

// ---------------------------------------------------------------------------
// Launcher
// ---------------------------------------------------------------------------
extern "C" void kernel_launch(void* const* d_in, const int* in_sizes, int n_in,
                              void* d_out, int out_size)
{
    const float* x    = (const float*)d_in[0];
    const float* fcos = (const float*)d_in[1];
    const float* fsin = (const float*)d_in[2];
    const float* Wq   = (const float*)d_in[3];
    const float* Wk   = (const float*)d_in[4];
    const float* Wv   = (const float*)d_in[5];
    const float* Wo   = (const float*)d_in[6];
    float* out = (float*)d_out;

    static bool init = false;
    if (!init) {
        cudaFuncSetAttribute(qkv_gemm, cudaFuncAttributeMaxDynamicSharedMemorySize, GEMM_SMEM);
        cudaFuncSetAttribute(gemm_out, cudaFuncAttributeMaxDynamicSharedMemorySize, GEMM_SMEM);
        cudaFuncSetAttribute(attn_mma, cudaFuncAttributeMaxDynamicSharedMemorySize, ATTN_SMEM);
        init = true;
    }

    // 1. prep: x -> fp16 A-frag; weights -> fp16 B-frag
    prep_x<<<1024, 256>>>(x);
    prep_w<<<2560, 256>>>(Wq, Wk, Wv, Wo);

    // 2. QKV projection + RoPE
    qkv_gemm<<<dim3(12, N_TOK / 128), 256, GEMM_SMEM>>>(fcos, fsin);

    // 3. Attention (all fp16 MMAs)
    attn_mma<<<dim3(N_TOK / 64, H_KV, 2), 256, ATTN_SMEM>>>();

    // 4. Output projection
    gemm_out<<<dim3(D_MODEL / 128, N_TOK / 128), 256, GEMM_SMEM>>>(out);
}

// round 11
// speedup vs baseline: 11.6772x; 1.0362x over previous
#include <cuda_runtime.h>
#include <math.h>
#include <stdint.h>

#define N_TOK   2048
#define D_MODEL 1024
#define H_Q     16
#define H_KV    4
#define HD      64
#define REPEATS (H_Q / H_KV)   // 4
#define QDIM    (H_Q * HD)     // 1024
#define KVDIM   (H_KV * HD)    // 256
#define QSCALE  0.1803368801111244f   // (1/sqrt(64)) * log2(e)

// scratch (allocation-free rule: __device__ globals), all fp16x2 words
// A-frag blob per [rowTile128][kTile32]: 512 uint4 = [mb(8)][kb(2)][lane(32)]
// B-frag blob per [colTile128][kTile32]: 1024 uint2 = [nb(16)][kb(2)][lane(32)]
__device__ uint32_t g_Xf [N_TOK * D_MODEL / 2];
__device__ uint32_t g_WqF[D_MODEL * QDIM / 2];
__device__ uint32_t g_WkF[D_MODEL * KVDIM / 2];
__device__ uint32_t g_WvF[D_MODEL * KVDIM / 2];
__device__ uint32_t g_WoF[QDIM * D_MODEL / 2];
__device__ uint32_t g_Qh [N_TOK * QDIM / 2];    // Q row-major fp16, RoPE'd, *QSCALE
__device__ uint32_t g_KFb[N_TOK * KVDIM / 2];   // K fp16, S-mma B-frag order
__device__ uint32_t g_VFh[N_TOK * KVDIM / 2];   // V fp16, PV-mma B-frag order
__device__ uint32_t g_Of [N_TOK * QDIM / 2];    // attention out, fp16 A-frag

// ---------------------------------------------------------------------------
// helpers
// ---------------------------------------------------------------------------
__device__ __forceinline__ uint16_t f2fp16(float f) {
    uint16_t r;
    asm("cvt.rn.f16.f32 %0, %1;" : "=h"(r) : "f"(f));
    return r;
}
__device__ __forceinline__ uint32_t packh2(float lo, float hi) {
    uint32_t r;
    asm("cvt.rn.f16x2.f32 %0, %1, %2;" : "=r"(r) : "f"(hi), "f"(lo));
    return r;
}
__device__ __forceinline__ float ex2f(float x) {
    float r;
    asm("ex2.approx.ftz.f32 %0, %1;" : "=f"(r) : "f"(x));
    return r;
}
__device__ __forceinline__ void mma_f16(float* d, uint32_t a0, uint32_t a1,
                                        uint32_t a2, uint32_t a3,
                                        uint32_t b0, uint32_t b1) {
    asm volatile(
        "mma.sync.aligned.m16n8k16.row.col.f32.f16.f16.f32 "
        "{%0,%1,%2,%3}, {%4,%5,%6,%7}, {%8,%9}, {%0,%1,%2,%3};"
        : "+f"(d[0]), "+f"(d[1]), "+f"(d[2]), "+f"(d[3])
        : "r"(a0), "r"(a1), "r"(a2), "r"(a3), "r"(b0), "r"(b1));
}
__device__ __forceinline__ void cp16(void* smem_dst, const void* gsrc) {
    uint32_t s = (uint32_t)__cvta_generic_to_shared(smem_dst);
    asm volatile("cp.async.cg.shared.global [%0], [%1], 16;" :: "r"(s), "l"(gsrc));
}
#define CP_COMMIT() asm volatile("cp.async.commit_group;")
#define CP_WAIT0()  asm volatile("cp.async.wait_group 0;")

// ---------------------------------------------------------------------------
// Prep (single kernel): x -> fp16 A-frag blobs; weights -> fp16 B-frag blobs
// ---------------------------------------------------------------------------
__global__ void prep_all(const float* __restrict__ x,
                         const float* __restrict__ Wq, const float* __restrict__ Wk,
                         const float* __restrict__ Wv, const float* __restrict__ Wo)
{
    // part 1: x (uint4 granularity)
    const int totX = N_TOK * D_MODEL / 8;
    for (int u = blockIdx.x * blockDim.x + threadIdx.x; u < totX;
         u += gridDim.x * blockDim.x) {
        int blob = u >> 9, widx = u & 511;
        int rt = blob >> 5, kt = blob & 31;
        int mb = widx >> 6, kb = (widx >> 5) & 1, lane = widx & 31;
        int g = lane >> 2, t = lane & 3;
        int r0 = rt * 128 + mb * 16 + g;
        int c0 = kt * 32 + kb * 16 + 2 * t;
        const float* xr0 = x + (size_t)r0 * D_MODEL;
        const float* xr8 = xr0 + (size_t)8 * D_MODEL;
        uint4 v;
        v.x = packh2(xr0[c0],     xr0[c0 + 1]);
        v.y = packh2(xr8[c0],     xr8[c0 + 1]);
        v.z = packh2(xr0[c0 + 8], xr0[c0 + 9]);
        v.w = packh2(xr8[c0 + 8], xr8[c0 + 9]);
        ((uint4*)g_Xf)[u] = v;
    }
    // part 2: weights (uint2 granularity)
    const int CQ = 262144, CK = 65536, CV = 65536, CO = 262144;
    const int totW = CQ + CK + CV + CO;
    for (int u = blockIdx.x * blockDim.x + threadIdx.x; u < totW;
         u += gridDim.x * blockDim.x) {
        const float* W; uint32_t* dst; int Nc; int off = u;
        if (off < CQ)              { W = Wq; dst = g_WqF; Nc = QDIM; }
        else if ((off -= CQ) < CK) { W = Wk; dst = g_WkF; Nc = KVDIM; }
        else if ((off -= CK) < CV) { W = Wv; dst = g_WvF; Nc = KVDIM; }
        else { off -= CV;            W = Wo; dst = g_WoF; Nc = D_MODEL; }
        int blob = off >> 10, widx = off & 1023;
        int ct = blob >> 5, kt = blob & 31;
        int nb = widx >> 6, kb = (widx >> 5) & 1, lane = widx & 31;
        int g = lane >> 2, t = lane & 3;
        int k0 = kt * 32 + kb * 16 + 2 * t;
        int n  = ct * 128 + nb * 8 + g;
        uint2 v;
        v.x = packh2(W[(size_t)k0 * Nc + n],       W[(size_t)(k0 + 1) * Nc + n]);
        v.y = packh2(W[(size_t)(k0 + 8) * Nc + n], W[(size_t)(k0 + 9) * Nc + n]);
        ((uint2*)dst)[off] = v;
    }
}

// Fragment-order scatter stores (consumed by attention)
__device__ __forceinline__ void storeK2(int kvh, int token, int dcol,
                                        float v0, float v1) {
    int tile = token >> 6, j = (token & 63) >> 3, gq = token & 7;
    int kf = dcol >> 4, r = dcol & 15;
    int e = r >> 3, tt = (r & 7) >> 1;
    size_t idx = ((size_t)((kvh * 32 + tile) * 32 + j * 4 + kf)) * 64
               + (gq * 4 + tt) * 2 + e;
    g_KFb[idx] = packh2(v0, v1);
}
__device__ __forceinline__ void storeV16(int kvh, int token, int dcol, uint16_t b) {
    int tile = token >> 6, kin = token & 63;
    int kbl = kin >> 4, kk = kin & 15;
    int half = kk >> 3, tt = (kk >> 1) & 3, e = kk & 1;
    int j = dcol >> 3, gg = dcol & 7;
    size_t word = ((size_t)(kvh * 32 + tile)) * 2048
                + ((kbl * 8 + j) * 32 + (gg * 4 + tt)) * 2 + half;
    ((uint16_t*)g_VFh)[word * 2 + e] = b;
}

// ---------------------------------------------------------------------------
// fp16 frag-layout GEMM: 128x128 tile, 256 thr, warps 2x4 (64x32 each),
// cp.async double-buffered. K = nkt*32.
// ---------------------------------------------------------------------------
#define GEMM_SMEM 32768

template<typename Epi>
__device__ __forceinline__ void gemm_frag(
    const uint32_t* __restrict__ A, const uint32_t* __restrict__ B,
    int rt, int ct, int nkt, char* smem, Epi&& epi)
{
    const int tid = threadIdx.x, lane = tid & 31, w = tid >> 5;
    const int wm = w >> 2, wn = w & 3, g = lane >> 2, t = lane & 3;
    uint32_t* sm32 = (uint32_t*)smem;

    float acc[4][4][4];
    #pragma unroll
    for (int mi = 0; mi < 4; mi++)
        #pragma unroll
        for (int nj = 0; nj < 4; nj++)
            #pragma unroll
            for (int r = 0; r < 4; r++) acc[mi][nj][r] = 0.0f;

    auto issue = [&](int kt, int bb) {
        const uint4* a4 = (const uint4*)(A + ((size_t)rt * nkt + kt) * 2048);
        const uint4* b4 = (const uint4*)(B + ((size_t)ct * nkt + kt) * 2048);
        uint32_t* dA = sm32 + bb * 4096;
        uint32_t* dB = dA + 2048;
        #pragma unroll
        for (int p = 0; p < 2; p++) {
            int i = tid + p * 256;
            cp16(&dA[i * 4], &a4[i]);
            cp16(&dB[i * 4], &b4[i]);
        }
        CP_COMMIT();
    };

    issue(0, 0);
    int stg = 0;
    for (int it = 0; it < nkt; it++) {
        CP_WAIT0();
        __syncthreads();
        if (it + 1 < nkt) issue(it + 1, stg ^ 1);

        const uint4* As4 = (const uint4*)(sm32 + stg * 4096);
        const uint2* Bs2 = (const uint2*)(sm32 + stg * 4096 + 2048);
        #pragma unroll
        for (int kb = 0; kb < 2; kb++) {
            uint4 af[4]; uint2 bf[4];
            #pragma unroll
            for (int mi = 0; mi < 4; mi++)
                af[mi] = As4[((wm * 4 + mi) * 2 + kb) * 32 + lane];
            #pragma unroll
            for (int nj = 0; nj < 4; nj++)
                bf[nj] = Bs2[((wn * 4 + nj) * 2 + kb) * 32 + lane];
            #pragma unroll
            for (int mi = 0; mi < 4; mi++)
                #pragma unroll
                for (int nj = 0; nj < 4; nj++)
                    mma_f16(acc[mi][nj], af[mi].x, af[mi].y, af[mi].z, af[mi].w,
                            bf[nj].x, bf[nj].y);
        }
        stg ^= 1;
    }

    #pragma unroll
    for (int mi = 0; mi < 4; mi++) {
        int row = rt * 128 + wm * 64 + mi * 16 + g;
        #pragma unroll
        for (int nj = 0; nj < 4; nj++) {
            int col = ct * 128 + wn * 32 + nj * 8 + 2 * t;
            epi(row, col, acc[mi][nj][0], acc[mi][nj][1],
                          acc[mi][nj][2], acc[mi][nj][3]);
        }
    }
}

// ---------------------------------------------------------------------------
// Fused QKV projection. grid (12, 16): bx<8 Q, bx<10 K, else V.
// ---------------------------------------------------------------------------
__global__ __launch_bounds__(256, 2) void qkv_gemm(
    const float* __restrict__ fcos, const float* __restrict__ fsin)
{
    extern __shared__ char smem[];
    const int bx = blockIdx.x, rt = blockIdx.y;

    if (bx < 8) {
        gemm_frag(g_Xf, g_WqF, rt, bx, 32, smem,
            [&](int row, int col, float v0, float v1, float v2, float v3) {
                int i = (col & 63) >> 1;
                float c0 = fcos[row * 32 + i],       s0 = fsin[row * 32 + i];
                float c1 = fcos[(row + 8) * 32 + i], s1 = fsin[(row + 8) * 32 + i];
                g_Qh[(size_t)row * 512 + (col >> 1)] = packh2(
                    (v0 * c0 - v1 * s0) * QSCALE, (v0 * s0 + v1 * c0) * QSCALE);
                g_Qh[(size_t)(row + 8) * 512 + (col >> 1)] = packh2(
                    (v2 * c1 - v3 * s1) * QSCALE, (v2 * s1 + v3 * c1) * QSCALE);
            });
    } else if (bx < 10) {
        gemm_frag(g_Xf, g_WkF, rt, bx - 8, 32, smem,
            [&](int row, int col, float v0, float v1, float v2, float v3) {
                int kvh = col >> 6, dcol = col & 63;
                int i = dcol >> 1;
                float c0 = fcos[row * 32 + i],       s0 = fsin[row * 32 + i];
                float c1 = fcos[(row + 8) * 32 + i], s1 = fsin[(row + 8) * 32 + i];
                storeK2(kvh, row,     dcol, v0 * c0 - v1 * s0, v0 * s0 + v1 * c0);
                storeK2(kvh, row + 8, dcol, v2 * c1 - v3 * s1, v2 * s1 + v3 * c1);
            });
    } else {
        gemm_frag(g_Xf, g_WvF, rt, bx - 10, 32, smem,
            [&](int row, int col, float v0, float v1, float v2, float v3) {
                int kvh = col >> 6, dcol = col & 63;
                storeV16(kvh, row,     dcol,     f2fp16(v0));
                storeV16(kvh, row,     dcol + 1, f2fp16(v1));
                storeV16(kvh, row + 8, dcol,     f2fp16(v2));
                storeV16(kvh, row + 8, dcol + 1, f2fp16(v3));
            });
    }
}

// Output projection: out = g_Of @ WoF, fp32 result.
__global__ __launch_bounds__(256, 2) void gemm_out(float* __restrict__ out)
{
    extern __shared__ char smem[];
    gemm_frag(g_Of, g_WoF, blockIdx.y, blockIdx.x, 32, smem,
        [&](int row, int col, float v0, float v1, float v2, float v3) {
            *(float2*)&out[(size_t)row * D_MODEL + col]       = make_float2(v0, v1);
            *(float2*)&out[(size_t)(row + 8) * D_MODEL + col] = make_float2(v2, v3);
        });
}

// ---------------------------------------------------------------------------
// FlashAttention-2, all-fp16 MMAs, base-2 softmax, zero shuffles.
// grid (32, H_KV, 4), 128 threads (4 warps = 1 head x 4 q-subtiles).
// Small CTAs -> 4 independent barrier domains per SM (latency hiding).
// ---------------------------------------------------------------------------
#define ATTN_SMEM (2 * 4096 * 4)   // 2 stages x (K 8KB + V 8KB)

__global__ __launch_bounds__(128) void attn_mma()
{
    extern __shared__ uint32_t sm[];

    const int kvh = blockIdx.y;
    const int tid = threadIdx.x;
    const int lane = tid & 31;
    const int w    = tid >> 5;                    // q-subtile 0..3
    const int g    = lane >> 2;
    const int t    = lane & 3;
    const int h    = kvh * REPEATS + blockIdx.z;  // 1 head per block
    const int qr0  = blockIdx.x * 64 + w * 16;
    const int tile0 = blockIdx.x;

    // Q fragments (fp16 pairs; RoPE'd, *QSCALE)
    uint32_t qf[4][4];
    {
        const uint32_t* q0 = g_Qh + (size_t)qr0 * 512 + h * 32;
        #pragma unroll
        for (int kf = 0; kf < 4; kf++) {
            qf[kf][0] = q0[(size_t)g       * 512 + kf * 8 + t];
            qf[kf][1] = q0[(size_t)(g + 8) * 512 + kf * 8 + t];
            qf[kf][2] = q0[(size_t)g       * 512 + kf * 8 + t + 4];
            qf[kf][3] = q0[(size_t)(g + 8) * 512 + kf * 8 + t + 4];
        }
    }

    float m0 = -INFINITY, m1 = -INFINITY, l0 = 0.0f, l1 = 0.0f;
    float o[8][4];
    #pragma unroll
    for (int j = 0; j < 8; j++)
        #pragma unroll
        for (int r = 0; r < 4; r++) o[j][r] = 0.0f;

    auto issue = [&](int tile, int stg) {
        const uint4* ks = (const uint4*)(g_KFb + (size_t)(kvh * 32 + tile) * 2048);
        const uint4* vs = (const uint4*)(g_VFh + (size_t)(kvh * 32 + tile) * 2048);
        uint32_t* dK = sm + stg * 4096;
        uint32_t* dV = dK + 2048;
        #pragma unroll
        for (int p = 0; p < 4; p++) {
            int i = tid + p * 128;
            cp16(&dK[i * 4], &ks[i]);
            cp16(&dV[i * 4], &vs[i]);
        }
        CP_COMMIT();
    };

    issue(tile0, 0);
    int stg = 0;
    for (int it = 0; it < 32; it++) {
        CP_WAIT0();
        __syncthreads();
        if (it + 1 < 32) issue((tile0 + it + 1) & 31, stg ^ 1);

        const uint2* KFs = (const uint2*)(sm + stg * 4096);
        const uint2* VFs = (const uint2*)(sm + stg * 4096 + 2048);

        // S = Q @ K^T (log2 units)
        float s[8][4];
        #pragma unroll
        for (int j = 0; j < 8; j++)
            #pragma unroll
            for (int r = 0; r < 4; r++) s[j][r] = 0.0f;
        #pragma unroll
        for (int kf = 0; kf < 4; kf++) {
            #pragma unroll
            for (int j = 0; j < 8; j++) {
                uint2 b = KFs[(j * 4 + kf) * 32 + lane];
                mma_f16(s[j], qf[kf][0], qf[kf][1], qf[kf][2], qf[kf][3], b.x, b.y);
            }
        }

        // Online softmax, base-2
        float tm0 = -INFINITY, tm1 = -INFINITY;
        #pragma unroll
        for (int j = 0; j < 8; j++) {
            tm0 = fmaxf(tm0, fmaxf(s[j][0], s[j][1]));
            tm1 = fmaxf(tm1, fmaxf(s[j][2], s[j][3]));
        }
        #pragma unroll
        for (int off = 1; off < 4; off <<= 1) {
            tm0 = fmaxf(tm0, __shfl_xor_sync(0xFFFFFFFF, tm0, off));
            tm1 = fmaxf(tm1, __shfl_xor_sync(0xFFFFFFFF, tm1, off));
        }
        float mn0 = fmaxf(m0, tm0), mn1 = fmaxf(m1, tm1);
        float c0 = ex2f(m0 - mn0), c1 = ex2f(m1 - mn1);
        l0 *= c0; l1 *= c1;
        #pragma unroll
        for (int j = 0; j < 8; j++) {
            o[j][0] *= c0; o[j][1] *= c0;
            o[j][2] *= c1; o[j][3] *= c1;
        }
        m0 = mn0; m1 = mn1;

        // P = 2^(s-m) packed fp16 (D-frag == A-frag pairing), O += P @ V
        #pragma unroll
        for (int kbl = 0; kbl < 4; kbl++) {
            float pa0 = ex2f(s[2 * kbl][0] - mn0),     pa1 = ex2f(s[2 * kbl][1] - mn0);
            float pa2 = ex2f(s[2 * kbl][2] - mn1),     pa3 = ex2f(s[2 * kbl][3] - mn1);
            float pb0 = ex2f(s[2 * kbl + 1][0] - mn0), pb1 = ex2f(s[2 * kbl + 1][1] - mn0);
            float pb2 = ex2f(s[2 * kbl + 1][2] - mn1), pb3 = ex2f(s[2 * kbl + 1][3] - mn1);
            l0 += pa0 + pa1 + pb0 + pb1;
            l1 += pa2 + pa3 + pb2 + pb3;
            uint32_t a0 = packh2(pa0, pa1);
            uint32_t a1 = packh2(pa2, pa3);
            uint32_t a2 = packh2(pb0, pb1);
            uint32_t a3 = packh2(pb2, pb3);
            #pragma unroll
            for (int j = 0; j < 8; j++) {
                uint2 vv = VFs[(kbl * 8 + j) * 32 + lane];
                mma_f16(o[j], a0, a1, a2, a3, vv.x, vv.y);
            }
        }
        stg ^= 1;
    }

    // Normalize + store as fp16 A-frag (no shuffles: D-pairs == A-pairs)
    #pragma unroll
    for (int off = 1; off < 4; off <<= 1) {
        l0 += __shfl_xor_sync(0xFFFFFFFF, l0, off);
        l1 += __shfl_xor_sync(0xFFFFFFFF, l1, off);
    }
    float inv0 = 1.0f / l0, inv1 = 1.0f / l1;
    const int rt = qr0 >> 7;
    const int mb = (qr0 >> 4) & 7;
    uint4* of4 = (uint4*)g_Of;
    #pragma unroll
    for (int jp = 0; jp < 4; jp++) {
        int j0 = 2 * jp, j1 = j0 + 1;
        uint4 a;
        a.x = packh2(o[j0][0] * inv0, o[j0][1] * inv0);
        a.y = packh2(o[j0][2] * inv1, o[j0][3] * inv1);
        a.z = packh2(o[j1][0] * inv0, o[j1][1] * inv0);
        a.w = packh2(o[j1][2] * inv1, o[j1][3] * inv1);
        int kt = h * 2 + (jp >> 1), kb = jp & 1;
        of4[((size_t)(rt * 32 + kt)) * 512 + (mb * 2 + kb) * 32 + lane] = a;
    }
}

// ---------------------------------------------------------------------------
// Launcher
// ---------------------------------------------------------------------------
extern "C" void kernel_launch(void* const* d_in, const int* in_sizes, int n_in,
                              void* d_out, int out_size)
{
    const float* x    = (const float*)d_in[0];
    const float* fcos = (const float*)d_in[1];
    const float* fsin = (const float*)d_in[2];
    const float* Wq   = (const float*)d_in[3];
    const float* Wk   = (const float*)d_in[4];
    const float* Wv   = (const float*)d_in[5];
    const float* Wo   = (const float*)d_in[6];
    float* out = (float*)d_out;

    static bool init = false;
    if (!init) {
        cudaFuncSetAttribute(qkv_gemm, cudaFuncAttributeMaxDynamicSharedMemorySize, GEMM_SMEM);
        cudaFuncSetAttribute(gemm_out, cudaFuncAttributeMaxDynamicSharedMemorySize, GEMM_SMEM);
        cudaFuncSetAttribute(attn_mma, cudaFuncAttributeMaxDynamicSharedMemorySize, ATTN_SMEM);
        init = true;
    }

    // 1. prep: x -> fp16 A-frag; weights -> fp16 B-frag (one kernel)
    prep_all<<<1480, 256>>>(x, Wq, Wk, Wv, Wo);

    // 2. QKV projection + RoPE
    qkv_gemm<<<dim3(12, N_TOK / 128), 256, GEMM_SMEM>>>(fcos, fsin);

    // 3. Attention (128-thread CTAs, 4 barrier domains per SM)
    attn_mma<<<dim3(N_TOK / 64, H_KV, REPEATS), 128, ATTN_SMEM>>>();

    // 4. Output projection
    gemm_out<<<dim3(D_MODEL / 128, N_TOK / 128), 256, GEMM_SMEM>>>(out);
}

// round 12
// speedup vs baseline: 12.3479x; 1.0574x over previous
#include <cuda_runtime.h>
#include <math.h>
#include <stdint.h>

#define N_TOK   2048
#define D_MODEL 1024
#define H_Q     16
#define H_KV    4
#define HD      64
#define REPEATS (H_Q / H_KV)   // 4
#define QDIM    (H_Q * HD)     // 1024
#define KVDIM   (H_KV * HD)    // 256
#define QSCALE  0.1803368801111244f   // (1/sqrt(64)) * log2(e)

// scratch (allocation-free rule: __device__ globals), all fp16x2 words
// A-frag blob per [rowTile128][kTile32]: 512 uint4 = [mb(8)][kb(2)][lane(32)]
// B-frag blob per [colTile128][kTile32]: 1024 uint2 = [nb(16)][kb(2)][lane(32)]
__device__ uint32_t g_Xf [N_TOK * D_MODEL / 2];
__device__ uint32_t g_WqF[D_MODEL * QDIM / 2];
__device__ uint32_t g_WkF[D_MODEL * KVDIM / 2];
__device__ uint32_t g_WvF[D_MODEL * KVDIM / 2];
__device__ uint32_t g_WoF[QDIM * D_MODEL / 2];
__device__ uint32_t g_Qh [N_TOK * QDIM / 2];    // Q row-major fp16, RoPE'd, *QSCALE
__device__ uint32_t g_KFb[N_TOK * KVDIM / 2];   // K fp16, S-mma B-frag order
__device__ uint32_t g_VFh[N_TOK * KVDIM / 2];   // V fp16, PV-mma B-frag order
__device__ uint32_t g_Of [N_TOK * QDIM / 2];    // attention out, fp16 A-frag

// ---------------------------------------------------------------------------
// helpers
// ---------------------------------------------------------------------------
__device__ __forceinline__ uint16_t f2fp16(float f) {
    uint16_t r;
    asm("cvt.rn.f16.f32 %0, %1;" : "=h"(r) : "f"(f));
    return r;
}
__device__ __forceinline__ uint32_t packh2(float lo, float hi) {
    uint32_t r;
    asm("cvt.rn.f16x2.f32 %0, %1, %2;" : "=r"(r) : "f"(hi), "f"(lo));
    return r;
}
__device__ __forceinline__ float ex2f(float x) {
    float r;
    asm("ex2.approx.ftz.f32 %0, %1;" : "=f"(r) : "f"(x));
    return r;
}
__device__ __forceinline__ void mma_f16(float* d, uint32_t a0, uint32_t a1,
                                        uint32_t a2, uint32_t a3,
                                        uint32_t b0, uint32_t b1) {
    asm volatile(
        "mma.sync.aligned.m16n8k16.row.col.f32.f16.f16.f32 "
        "{%0,%1,%2,%3}, {%4,%5,%6,%7}, {%8,%9}, {%0,%1,%2,%3};"
        : "+f"(d[0]), "+f"(d[1]), "+f"(d[2]), "+f"(d[3])
        : "r"(a0), "r"(a1), "r"(a2), "r"(a3), "r"(b0), "r"(b1));
}
__device__ __forceinline__ void cp16(void* smem_dst, const void* gsrc) {
    uint32_t s = (uint32_t)__cvta_generic_to_shared(smem_dst);
    asm volatile("cp.async.cg.shared.global [%0], [%1], 16;" :: "r"(s), "l"(gsrc));
}
#define CP_COMMIT() asm volatile("cp.async.commit_group;")
#define CP_WAIT0()  asm volatile("cp.async.wait_group 0;")

// ---------------------------------------------------------------------------
// Prep (single kernel): x -> fp16 A-frag blobs; weights -> fp16 B-frag blobs
// ---------------------------------------------------------------------------
__global__ void prep_all(const float* __restrict__ x,
                         const float* __restrict__ Wq, const float* __restrict__ Wk,
                         const float* __restrict__ Wv, const float* __restrict__ Wo)
{
    const int totX = N_TOK * D_MODEL / 8;
    for (int u = blockIdx.x * blockDim.x + threadIdx.x; u < totX;
         u += gridDim.x * blockDim.x) {
        int blob = u >> 9, widx = u & 511;
        int rt = blob >> 5, kt = blob & 31;
        int mb = widx >> 6, kb = (widx >> 5) & 1, lane = widx & 31;
        int g = lane >> 2, t = lane & 3;
        int r0 = rt * 128 + mb * 16 + g;
        int c0 = kt * 32 + kb * 16 + 2 * t;
        const float* xr0 = x + (size_t)r0 * D_MODEL;
        const float* xr8 = xr0 + (size_t)8 * D_MODEL;
        uint4 v;
        v.x = packh2(xr0[c0],     xr0[c0 + 1]);
        v.y = packh2(xr8[c0],     xr8[c0 + 1]);
        v.z = packh2(xr0[c0 + 8], xr0[c0 + 9]);
        v.w = packh2(xr8[c0 + 8], xr8[c0 + 9]);
        ((uint4*)g_Xf)[u] = v;
    }
    const int CQ = 262144, CK = 65536, CV = 65536, CO = 262144;
    const int totW = CQ + CK + CV + CO;
    for (int u = blockIdx.x * blockDim.x + threadIdx.x; u < totW;
         u += gridDim.x * blockDim.x) {
        const float* W; uint32_t* dst; int Nc; int off = u;
        if (off < CQ)              { W = Wq; dst = g_WqF; Nc = QDIM; }
        else if ((off -= CQ) < CK) { W = Wk; dst = g_WkF; Nc = KVDIM; }
        else if ((off -= CK) < CV) { W = Wv; dst = g_WvF; Nc = KVDIM; }
        else { off -= CV;            W = Wo; dst = g_WoF; Nc = D_MODEL; }
        int blob = off >> 10, widx = off & 1023;
        int ct = blob >> 5, kt = blob & 31;
        int nb = widx >> 6, kb = (widx >> 5) & 1, lane = widx & 31;
        int g = lane >> 2, t = lane & 3;
        int k0 = kt * 32 + kb * 16 + 2 * t;
        int n  = ct * 128 + nb * 8 + g;
        uint2 v;
        v.x = packh2(W[(size_t)k0 * Nc + n],       W[(size_t)(k0 + 1) * Nc + n]);
        v.y = packh2(W[(size_t)(k0 + 8) * Nc + n], W[(size_t)(k0 + 9) * Nc + n]);
        ((uint2*)dst)[off] = v;
    }
}

// Fragment-order scatter stores (consumed by attention)
__device__ __forceinline__ void storeK2(int kvh, int token, int dcol,
                                        float v0, float v1) {
    int tile = token >> 6, j = (token & 63) >> 3, gq = token & 7;
    int kf = dcol >> 4, r = dcol & 15;
    int e = r >> 3, tt = (r & 7) >> 1;
    size_t idx = ((size_t)((kvh * 32 + tile) * 32 + j * 4 + kf)) * 64
               + (gq * 4 + tt) * 2 + e;
    g_KFb[idx] = packh2(v0, v1);
}
__device__ __forceinline__ void storeV16(int kvh, int token, int dcol, uint16_t b) {
    int tile = token >> 6, kin = token & 63;
    int kbl = kin >> 4, kk = kin & 15;
    int half = kk >> 3, tt = (kk >> 1) & 3, e = kk & 1;
    int j = dcol >> 3, gg = dcol & 7;
    size_t word = ((size_t)(kvh * 32 + tile)) * 2048
                + ((kbl * 8 + j) * 32 + (gg * 4 + tt)) * 2 + half;
    ((uint16_t*)g_VFh)[word * 2 + e] = b;
}

// ---------------------------------------------------------------------------
// fp16 frag-layout GEMM: 128x64 tile, 256 thr, warps 4x2 (32x32 each),
// cp.async double-buffered. K = nkt*32. ct64 indexes 64-col tiles; a 64-col
// tile is the contiguous half (nb 0-7 / 8-15) of a 128-col B-frag blob.
// ---------------------------------------------------------------------------
#define GEMM_SMEM 24576   // 2 stages x (A 8KB + B 4KB)

template<typename Epi>
__device__ __forceinline__ void gemm_frag(
    const uint32_t* __restrict__ A, const uint32_t* __restrict__ B,
    int rt, int ct64, int nkt, char* smem, Epi&& epi)
{
    const int tid = threadIdx.x, lane = tid & 31, w = tid >> 5;
    const int wm = w >> 1, wn = w & 1, g = lane >> 2, t = lane & 3;
    uint32_t* sm32 = (uint32_t*)smem;
    const size_t bBlob = ((size_t)(ct64 >> 1) * nkt) * 2048 + (ct64 & 1) * 1024;

    float acc[2][4][4];
    #pragma unroll
    for (int mi = 0; mi < 2; mi++)
        #pragma unroll
        for (int nj = 0; nj < 4; nj++)
            #pragma unroll
            for (int r = 0; r < 4; r++) acc[mi][nj][r] = 0.0f;

    auto issue = [&](int kt, int bb) {
        const uint4* a4 = (const uint4*)(A + ((size_t)rt * nkt + kt) * 2048);
        const uint4* b4 = (const uint4*)(B + bBlob + (size_t)kt * 2048);
        uint32_t* dA = sm32 + bb * 3072;
        uint32_t* dB = dA + 2048;
        #pragma unroll
        for (int p = 0; p < 2; p++)
            cp16(&dA[(tid + p * 256) * 4], &a4[tid + p * 256]);
        cp16(&dB[tid * 4], &b4[tid]);
        CP_COMMIT();
    };

    issue(0, 0);
    int stg = 0;
    for (int it = 0; it < nkt; it++) {
        CP_WAIT0();
        __syncthreads();
        if (it + 1 < nkt) issue(it + 1, stg ^ 1);

        const uint4* As4 = (const uint4*)(sm32 + stg * 3072);
        const uint2* Bs2 = (const uint2*)(sm32 + stg * 3072 + 2048);
        #pragma unroll
        for (int kb = 0; kb < 2; kb++) {
            uint4 af[2]; uint2 bf[4];
            #pragma unroll
            for (int mi = 0; mi < 2; mi++)
                af[mi] = As4[((wm * 2 + mi) * 2 + kb) * 32 + lane];
            #pragma unroll
            for (int nj = 0; nj < 4; nj++)
                bf[nj] = Bs2[((wn * 4 + nj) * 2 + kb) * 32 + lane];
            #pragma unroll
            for (int mi = 0; mi < 2; mi++)
                #pragma unroll
                for (int nj = 0; nj < 4; nj++)
                    mma_f16(acc[mi][nj], af[mi].x, af[mi].y, af[mi].z, af[mi].w,
                            bf[nj].x, bf[nj].y);
        }
        stg ^= 1;
    }

    #pragma unroll
    for (int mi = 0; mi < 2; mi++) {
        int row = rt * 128 + wm * 32 + mi * 16 + g;
        #pragma unroll
        for (int nj = 0; nj < 4; nj++) {
            int col = ct64 * 64 + wn * 32 + nj * 8 + 2 * t;
            epi(row, col, acc[mi][nj][0], acc[mi][nj][1],
                          acc[mi][nj][2], acc[mi][nj][3]);
        }
    }
}

// ---------------------------------------------------------------------------
// Fused QKV projection. grid (24, 16): bx<16 Q, bx<20 K, else V.
// ---------------------------------------------------------------------------
__global__ __launch_bounds__(256) void qkv_gemm(
    const float* __restrict__ fcos, const float* __restrict__ fsin)
{
    extern __shared__ char smem[];
    const int bx = blockIdx.x, rt = blockIdx.y;

    if (bx < 16) {
        gemm_frag(g_Xf, g_WqF, rt, bx, 32, smem,
            [&](int row, int col, float v0, float v1, float v2, float v3) {
                int i = (col & 63) >> 1;
                float c0 = fcos[row * 32 + i],       s0 = fsin[row * 32 + i];
                float c1 = fcos[(row + 8) * 32 + i], s1 = fsin[(row + 8) * 32 + i];
                g_Qh[(size_t)row * 512 + (col >> 1)] = packh2(
                    (v0 * c0 - v1 * s0) * QSCALE, (v0 * s0 + v1 * c0) * QSCALE);
                g_Qh[(size_t)(row + 8) * 512 + (col >> 1)] = packh2(
                    (v2 * c1 - v3 * s1) * QSCALE, (v2 * s1 + v3 * c1) * QSCALE);
            });
    } else if (bx < 20) {
        gemm_frag(g_Xf, g_WkF, rt, bx - 16, 32, smem,
            [&](int row, int col, float v0, float v1, float v2, float v3) {
                int kvh = col >> 6, dcol = col & 63;
                int i = dcol >> 1;
                float c0 = fcos[row * 32 + i],       s0 = fsin[row * 32 + i];
                float c1 = fcos[(row + 8) * 32 + i], s1 = fsin[(row + 8) * 32 + i];
                storeK2(kvh, row,     dcol, v0 * c0 - v1 * s0, v0 * s0 + v1 * c0);
                storeK2(kvh, row + 8, dcol, v2 * c1 - v3 * s1, v2 * s1 + v3 * c1);
            });
    } else {
        gemm_frag(g_Xf, g_WvF, rt, bx - 20, 32, smem,
            [&](int row, int col, float v0, float v1, float v2, float v3) {
                int kvh = col >> 6, dcol = col & 63;
                storeV16(kvh, row,     dcol,     f2fp16(v0));
                storeV16(kvh, row,     dcol + 1, f2fp16(v1));
                storeV16(kvh, row + 8, dcol,     f2fp16(v2));
                storeV16(kvh, row + 8, dcol + 1, f2fp16(v3));
            });
    }
}

// Output projection: out = g_Of @ WoF, fp32 result. grid (16, 16).
__global__ __launch_bounds__(256) void gemm_out(float* __restrict__ out)
{
    extern __shared__ char smem[];
    gemm_frag(g_Of, g_WoF, blockIdx.y, blockIdx.x, 32, smem,
        [&](int row, int col, float v0, float v1, float v2, float v3) {
            *(float2*)&out[(size_t)row * D_MODEL + col]       = make_float2(v0, v1);
            *(float2*)&out[(size_t)(row + 8) * D_MODEL + col] = make_float2(v2, v3);
        });
}

// ---------------------------------------------------------------------------
// FlashAttention-2, all-fp16 MMAs, base-2 softmax, zero shuffles.
// grid (32, H_KV, 4), 128 threads (4 warps = 1 head x 4 q-subtiles).
// ---------------------------------------------------------------------------
#define ATTN_SMEM (2 * 4096 * 4)   // 2 stages x (K 8KB + V 8KB)

__global__ __launch_bounds__(128) void attn_mma()
{
    extern __shared__ uint32_t sm[];

    const int kvh = blockIdx.y;
    const int tid = threadIdx.x;
    const int lane = tid & 31;
    const int w    = tid >> 5;
    const int g    = lane >> 2;
    const int t    = lane & 3;
    const int h    = kvh * REPEATS + blockIdx.z;
    const int qr0  = blockIdx.x * 64 + w * 16;
    const int tile0 = blockIdx.x;

    uint32_t qf[4][4];
    {
        const uint32_t* q0 = g_Qh + (size_t)qr0 * 512 + h * 32;
        #pragma unroll
        for (int kf = 0; kf < 4; kf++) {
            qf[kf][0] = q0[(size_t)g       * 512 + kf * 8 + t];
            qf[kf][1] = q0[(size_t)(g + 8) * 512 + kf * 8 + t];
            qf[kf][2] = q0[(size_t)g       * 512 + kf * 8 + t + 4];
            qf[kf][3] = q0[(size_t)(g + 8) * 512 + kf * 8 + t + 4];
        }
    }

    float m0 = -INFINITY, m1 = -INFINITY, l0 = 0.0f, l1 = 0.0f;
    float o[8][4];
    #pragma unroll
    for (int j = 0; j < 8; j++)
        #pragma unroll
        for (int r = 0; r < 4; r++) o[j][r] = 0.0f;

    auto issue = [&](int tile, int stg) {
        const uint4* ks = (const uint4*)(g_KFb + (size_t)(kvh * 32 + tile) * 2048);
        const uint4* vs = (const uint4*)(g_VFh + (size_t)(kvh * 32 + tile) * 2048);
        uint32_t* dK = sm + stg * 4096;
        uint32_t* dV = dK + 2048;
        #pragma unroll
        for (int p = 0; p < 4; p++) {
            int i = tid + p * 128;
            cp16(&dK[i * 4], &ks[i]);
            cp16(&dV[i * 4], &vs[i]);
        }
        CP_COMMIT();
    };

    issue(tile0, 0);
    int stg = 0;
    for (int it = 0; it < 32; it++) {
        CP_WAIT0();
        __syncthreads();
        if (it + 1 < 32) issue((tile0 + it + 1) & 31, stg ^ 1);

        const uint2* KFs = (const uint2*)(sm + stg * 4096);
        const uint2* VFs = (const uint2*)(sm + stg * 4096 + 2048);

        float s[8][4];
        #pragma unroll
        for (int j = 0; j < 8; j++)
            #pragma unroll
            for (int r = 0; r < 4; r++) s[j][r] = 0.0f;
        #pragma unroll
        for (int kf = 0; kf < 4; kf++) {
            #pragma unroll
            for (int j = 0; j < 8; j++) {
                uint2 b = KFs[(j * 4 + kf) * 32 + lane];
                mma_f16(s[j], qf[kf][0], qf[kf][1], qf[kf][2], qf[kf][3], b.x, b.y);
            }
        }

        float tm0 = -INFINITY, tm1 = -INFINITY;
        #pragma unroll
        for (int j = 0; j < 8; j++) {
            tm0 = fmaxf(tm0, fmaxf(s[j][0], s[j][1]));
            tm1 = fmaxf(tm1, fmaxf(s[j][2], s[j][3]));
        }
        #pragma unroll
        for (int off = 1; off < 4; off <<= 1) {
            tm0 = fmaxf(tm0, __shfl_xor_sync(0xFFFFFFFF, tm0, off));
            tm1 = fmaxf(tm1, __shfl_xor_sync(0xFFFFFFFF, tm1, off));
        }
        float mn0 = fmaxf(m0, tm0), mn1 = fmaxf(m1, tm1);
        float c0 = ex2f(m0 - mn0), c1 = ex2f(m1 - mn1);
        l0 *= c0; l1 *= c1;
        #pragma unroll
        for (int j = 0; j < 8; j++) {
            o[j][0] *= c0; o[j][1] *= c0;
            o[j][2] *= c1; o[j][3] *= c1;
        }
        m0 = mn0; m1 = mn1;

        #pragma unroll
        for (int kbl = 0; kbl < 4; kbl++) {
            float pa0 = ex2f(s[2 * kbl][0] - mn0),     pa1 = ex2f(s[2 * kbl][1] - mn0);
            float pa2 = ex2f(s[2 * kbl][2] - mn1),     pa3 = ex2f(s[2 * kbl][3] - mn1);
            float pb0 = ex2f(s[2 * kbl + 1][0] - mn0), pb1 = ex2f(s[2 * kbl + 1][1] - mn0);
            float pb2 = ex2f(s[2 * kbl + 1][2] - mn1), pb3 = ex2f(s[2 * kbl + 1][3] - mn1);
            l0 += pa0 + pa1 + pb0 + pb1;
            l1 += pa2 + pa3 + pb2 + pb3;
            uint32_t a0 = packh2(pa0, pa1);
            uint32_t a1 = packh2(pa2, pa3);
            uint32_t a2 = packh2(pb0, pb1);
            uint32_t a3 = packh2(pb2, pb3);
            #pragma unroll
            for (int j = 0; j < 8; j++) {
                uint2 vv = VFs[(kbl * 8 + j) * 32 + lane];
                mma_f16(o[j], a0, a1, a2, a3, vv.x, vv.y);
            }
        }
        stg ^= 1;
    }

    #pragma unroll
    for (int off = 1; off < 4; off <<= 1) {
        l0 += __shfl_xor_sync(0xFFFFFFFF, l0, off);
        l1 += __shfl_xor_sync(0xFFFFFFFF, l1, off);
    }
    float inv0 = 1.0f / l0, inv1 = 1.0f / l1;
    const int rt = qr0 >> 7;
    const int mb = (qr0 >> 4) & 7;
    uint4* of4 = (uint4*)g_Of;
    #pragma unroll
    for (int jp = 0; jp < 4; jp++) {
        int j0 = 2 * jp, j1 = j0 + 1;
        uint4 a;
        a.x = packh2(o[j0][0] * inv0, o[j0][1] * inv0);
        a.y = packh2(o[j0][2] * inv1, o[j0][3] * inv1);
        a.z = packh2(o[j1][0] * inv0, o[j1][1] * inv0);
        a.w = packh2(o[j1][2] * inv1, o[j1][3] * inv1);
        int kt = h * 2 + (jp >> 1), kb = jp & 1;
        of4[((size_t)(rt * 32 + kt)) * 512 + (mb * 2 + kb) * 32 + lane] = a;
    }
}

// ---------------------------------------------------------------------------
// Launcher
// ---------------------------------------------------------------------------
extern "C" void kernel_launch(void* const* d_in, const int* in_sizes, int n_in,
                              void* d_out, int out_size)
{
    const float* x    = (const float*)d_in[0];
    const float* fcos = (const float*)d_in[1];
    const float* fsin = (const float*)d_in[2];
    const float* Wq   = (const float*)d_in[3];
    const float* Wk   = (const float*)d_in[4];
    const float* Wv   = (const float*)d_in[5];
    const float* Wo   = (const float*)d_in[6];
    float* out = (float*)d_out;

    static bool init = false;
    if (!init) {
        cudaFuncSetAttribute(qkv_gemm, cudaFuncAttributeMaxDynamicSharedMemorySize, GEMM_SMEM);
        cudaFuncSetAttribute(gemm_out, cudaFuncAttributeMaxDynamicSharedMemorySize, GEMM_SMEM);
        cudaFuncSetAttribute(attn_mma, cudaFuncAttributeMaxDynamicSharedMemorySize, ATTN_SMEM);
        init = true;
    }

    // 1. prep: x -> fp16 A-frag; weights -> fp16 B-frag
    prep_all<<<1480, 256>>>(x, Wq, Wk, Wv, Wo);

    // 2. QKV projection + RoPE (128x64 tiles, 384 blocks)
    qkv_gemm<<<dim3(24, N_TOK / 128), 256, GEMM_SMEM>>>(fcos, fsin);

    // 3. Attention
    attn_mma<<<dim3(N_TOK / 64, H_KV, REPEATS), 128, ATTN_SMEM>>>();

    // 4. Output projection (128x64 tiles, 256 blocks)
    gemm_out<<<dim3(D_MODEL / 64, N_TOK / 128), 256, GEMM_SMEM>>>(out);
}

// round 13
// speedup vs baseline: 12.6506x; 1.0245x over previous
#include <cuda_runtime.h>
#include <math.h>
#include <stdint.h>

#define N_TOK   2048
#define D_MODEL 1024
#define H_Q     16
#define H_KV    4
#define HD      64
#define REPEATS (H_Q / H_KV)   // 4
#define QDIM    (H_Q * HD)     // 1024
#define KVDIM   (H_KV * HD)    // 256
#define QSCALE  0.1803368801111244f   // (1/sqrt(64)) * log2(e)

// scratch (allocation-free rule: __device__ globals), all fp16x2 words
// A-frag blob per [rowTile128][kTile32]: 512 uint4 = [mb(8)][kb(2)][lane(32)]
// B-frag blob per [colTile128][kTile32]: 1024 uint2 = [nb(16)][kb(2)][lane(32)]
__device__ uint32_t g_Xf [N_TOK * D_MODEL / 2];
__device__ uint32_t g_WqF[D_MODEL * QDIM / 2];
__device__ uint32_t g_WkF[D_MODEL * KVDIM / 2];
__device__ uint32_t g_WvF[D_MODEL * KVDIM / 2];
__device__ uint32_t g_WoF[QDIM * D_MODEL / 2];
__device__ uint32_t g_Qh [N_TOK * QDIM / 2];    // Q row-major fp16, RoPE'd, *QSCALE
__device__ uint32_t g_KFb[N_TOK * KVDIM / 2];   // K fp16, S-mma B-frag order
__device__ uint32_t g_VFh[N_TOK * KVDIM / 2];   // V fp16, PV-mma B-frag order
__device__ uint32_t g_Of [N_TOK * QDIM / 2];    // attention out, fp16 A-frag

// ---------------------------------------------------------------------------
// helpers
// ---------------------------------------------------------------------------
__device__ __forceinline__ uint16_t f2fp16(float f) {
    uint16_t r;
    asm("cvt.rn.f16.f32 %0, %1;" : "=h"(r) : "f"(f));
    return r;
}
__device__ __forceinline__ uint32_t packh2(float lo, float hi) {
    uint32_t r;
    asm("cvt.rn.f16x2.f32 %0, %1, %2;" : "=r"(r) : "f"(hi), "f"(lo));
    return r;
}
__device__ __forceinline__ float ex2f(float x) {
    float r;
    asm("ex2.approx.ftz.f32 %0, %1;" : "=f"(r) : "f"(x));
    return r;
}
__device__ __forceinline__ void mma_f16(float* d, uint32_t a0, uint32_t a1,
                                        uint32_t a2, uint32_t a3,
                                        uint32_t b0, uint32_t b1) {
    asm volatile(
        "mma.sync.aligned.m16n8k16.row.col.f32.f16.f16.f32 "
        "{%0,%1,%2,%3}, {%4,%5,%6,%7}, {%8,%9}, {%0,%1,%2,%3};"
        : "+f"(d[0]), "+f"(d[1]), "+f"(d[2]), "+f"(d[3])
        : "r"(a0), "r"(a1), "r"(a2), "r"(a3), "r"(b0), "r"(b1));
}
__device__ __forceinline__ void cp16(void* smem_dst, const void* gsrc) {
    uint32_t s = (uint32_t)__cvta_generic_to_shared(smem_dst);
    asm volatile("cp.async.cg.shared.global [%0], [%1], 16;" :: "r"(s), "l"(gsrc));
}
#define CP_COMMIT() asm volatile("cp.async.commit_group;")
#define CP_WAIT_1() asm volatile("cp.async.wait_group 1;")

// ---------------------------------------------------------------------------
// Prep (single kernel): x -> fp16 A-frag blobs; weights -> fp16 B-frag blobs
// ---------------------------------------------------------------------------
__global__ void prep_all(const float* __restrict__ x,
                         const float* __restrict__ Wq, const float* __restrict__ Wk,
                         const float* __restrict__ Wv, const float* __restrict__ Wo)
{
    const int totX = N_TOK * D_MODEL / 8;
    for (int u = blockIdx.x * blockDim.x + threadIdx.x; u < totX;
         u += gridDim.x * blockDim.x) {
        int blob = u >> 9, widx = u & 511;
        int rt = blob >> 5, kt = blob & 31;
        int mb = widx >> 6, kb = (widx >> 5) & 1, lane = widx & 31;
        int g = lane >> 2, t = lane & 3;
        int r0 = rt * 128 + mb * 16 + g;
        int c0 = kt * 32 + kb * 16 + 2 * t;
        const float* xr0 = x + (size_t)r0 * D_MODEL;
        const float* xr8 = xr0 + (size_t)8 * D_MODEL;
        uint4 v;
        v.x = packh2(xr0[c0],     xr0[c0 + 1]);
        v.y = packh2(xr8[c0],     xr8[c0 + 1]);
        v.z = packh2(xr0[c0 + 8], xr0[c0 + 9]);
        v.w = packh2(xr8[c0 + 8], xr8[c0 + 9]);
        ((uint4*)g_Xf)[u] = v;
    }
    const int CQ = 262144, CK = 65536, CV = 65536, CO = 262144;
    const int totW = CQ + CK + CV + CO;
    for (int u = blockIdx.x * blockDim.x + threadIdx.x; u < totW;
         u += gridDim.x * blockDim.x) {
        const float* W; uint32_t* dst; int Nc; int off = u;
        if (off < CQ)              { W = Wq; dst = g_WqF; Nc = QDIM; }
        else if ((off -= CQ) < CK) { W = Wk; dst = g_WkF; Nc = KVDIM; }
        else if ((off -= CK) < CV) { W = Wv; dst = g_WvF; Nc = KVDIM; }
        else { off -= CV;            W = Wo; dst = g_WoF; Nc = D_MODEL; }
        int blob = off >> 10, widx = off & 1023;
        int ct = blob >> 5, kt = blob & 31;
        int nb = widx >> 6, kb = (widx >> 5) & 1, lane = widx & 31;
        int g = lane >> 2, t = lane & 3;
        int k0 = kt * 32 + kb * 16 + 2 * t;
        int n  = ct * 128 + nb * 8 + g;
        uint2 v;
        v.x = packh2(W[(size_t)k0 * Nc + n],       W[(size_t)(k0 + 1) * Nc + n]);
        v.y = packh2(W[(size_t)(k0 + 8) * Nc + n], W[(size_t)(k0 + 9) * Nc + n]);
        ((uint2*)dst)[off] = v;
    }
}

// Fragment-order scatter stores (consumed by attention)
__device__ __forceinline__ void storeK2(int kvh, int token, int dcol,
                                        float v0, float v1) {
    int tile = token >> 6, j = (token & 63) >> 3, gq = token & 7;
    int kf = dcol >> 4, r = dcol & 15;
    int e = r >> 3, tt = (r & 7) >> 1;
    size_t idx = ((size_t)((kvh * 32 + tile) * 32 + j * 4 + kf)) * 64
               + (gq * 4 + tt) * 2 + e;
    g_KFb[idx] = packh2(v0, v1);
}
__device__ __forceinline__ void storeV16(int kvh, int token, int dcol, uint16_t b) {
    int tile = token >> 6, kin = token & 63;
    int kbl = kin >> 4, kk = kin & 15;
    int half = kk >> 3, tt = (kk >> 1) & 3, e = kk & 1;
    int j = dcol >> 3, gg = dcol & 7;
    size_t word = ((size_t)(kvh * 32 + tile)) * 2048
                + ((kbl * 8 + j) * 32 + (gg * 4 + tt)) * 2 + half;
    ((uint16_t*)g_VFh)[word * 2 + e] = b;
}

// ---------------------------------------------------------------------------
// fp16 frag-layout GEMM: 128x64 tile, 256 thr, warps 4x2 (32x32 each),
// 3-stage cp.async pipeline (wait_group 1). K = nkt*32.
// ---------------------------------------------------------------------------
#define GEMM_SMEM (3 * 3072 * 4)   // 3 stages x (A 8KB + B 4KB)

template<typename Epi>
__device__ __forceinline__ void gemm_frag(
    const uint32_t* __restrict__ A, const uint32_t* __restrict__ B,
    int rt, int ct64, int nkt, char* smem, Epi&& epi)
{
    const int tid = threadIdx.x, lane = tid & 31, w = tid >> 5;
    const int wm = w >> 1, wn = w & 1, g = lane >> 2, t = lane & 3;
    uint32_t* sm32 = (uint32_t*)smem;
    const size_t bBlob = ((size_t)(ct64 >> 1) * nkt) * 2048 + (ct64 & 1) * 1024;

    float acc[2][4][4];
    #pragma unroll
    for (int mi = 0; mi < 2; mi++)
        #pragma unroll
        for (int nj = 0; nj < 4; nj++)
            #pragma unroll
            for (int r = 0; r < 4; r++) acc[mi][nj][r] = 0.0f;

    auto issue = [&](int kt, int bb) {
        const uint4* a4 = (const uint4*)(A + ((size_t)rt * nkt + kt) * 2048);
        const uint4* b4 = (const uint4*)(B + bBlob + (size_t)kt * 2048);
        uint32_t* dA = sm32 + bb * 3072;
        uint32_t* dB = dA + 2048;
        #pragma unroll
        for (int p = 0; p < 2; p++)
            cp16(&dA[(tid + p * 256) * 4], &a4[tid + p * 256]);
        cp16(&dB[tid * 4], &b4[tid]);
        CP_COMMIT();
    };

    issue(0, 0);
    issue(1, 1);
    for (int it = 0; it < nkt; it++) {
        const int stg = it % 3;
        CP_WAIT_1();
        __syncthreads();

        const uint4* As4 = (const uint4*)(sm32 + stg * 3072);
        const uint2* Bs2 = (const uint2*)(sm32 + stg * 3072 + 2048);
        #pragma unroll
        for (int kb = 0; kb < 2; kb++) {
            uint4 af[2]; uint2 bf[4];
            #pragma unroll
            for (int mi = 0; mi < 2; mi++)
                af[mi] = As4[((wm * 2 + mi) * 2 + kb) * 32 + lane];
            #pragma unroll
            for (int nj = 0; nj < 4; nj++)
                bf[nj] = Bs2[((wn * 4 + nj) * 2 + kb) * 32 + lane];
            #pragma unroll
            for (int mi = 0; mi < 2; mi++)
                #pragma unroll
                for (int nj = 0; nj < 4; nj++)
                    mma_f16(acc[mi][nj], af[mi].x, af[mi].y, af[mi].z, af[mi].w,
                            bf[nj].x, bf[nj].y);
        }
        if (it + 2 < nkt) issue(it + 2, (it + 2) % 3);
        else CP_COMMIT();   // empty group keeps wait_group accounting uniform
    }

    #pragma unroll
    for (int mi = 0; mi < 2; mi++) {
        int row = rt * 128 + wm * 32 + mi * 16 + g;
        #pragma unroll
        for (int nj = 0; nj < 4; nj++) {
            int col = ct64 * 64 + wn * 32 + nj * 8 + 2 * t;
            epi(row, col, acc[mi][nj][0], acc[mi][nj][1],
                          acc[mi][nj][2], acc[mi][nj][3]);
        }
    }
}

// ---------------------------------------------------------------------------
// Fused QKV projection. grid (24, 16): bx<16 Q, bx<20 K, else V.
// ---------------------------------------------------------------------------
__global__ __launch_bounds__(256) void qkv_gemm(
    const float* __restrict__ fcos, const float* __restrict__ fsin)
{
    extern __shared__ char smem[];
    const int bx = blockIdx.x, rt = blockIdx.y;

    if (bx < 16) {
        gemm_frag(g_Xf, g_WqF, rt, bx, 32, smem,
            [&](int row, int col, float v0, float v1, float v2, float v3) {
                int i = (col & 63) >> 1;
                float c0 = fcos[row * 32 + i],       s0 = fsin[row * 32 + i];
                float c1 = fcos[(row + 8) * 32 + i], s1 = fsin[(row + 8) * 32 + i];
                g_Qh[(size_t)row * 512 + (col >> 1)] = packh2(
                    (v0 * c0 - v1 * s0) * QSCALE, (v0 * s0 + v1 * c0) * QSCALE);
                g_Qh[(size_t)(row + 8) * 512 + (col >> 1)] = packh2(
                    (v2 * c1 - v3 * s1) * QSCALE, (v2 * s1 + v3 * c1) * QSCALE);
            });
    } else if (bx < 20) {
        gemm_frag(g_Xf, g_WkF, rt, bx - 16, 32, smem,
            [&](int row, int col, float v0, float v1, float v2, float v3) {
                int kvh = col >> 6, dcol = col & 63;
                int i = dcol >> 1;
                float c0 = fcos[row * 32 + i],       s0 = fsin[row * 32 + i];
                float c1 = fcos[(row + 8) * 32 + i], s1 = fsin[(row + 8) * 32 + i];
                storeK2(kvh, row,     dcol, v0 * c0 - v1 * s0, v0 * s0 + v1 * c0);
                storeK2(kvh, row + 8, dcol, v2 * c1 - v3 * s1, v2 * s1 + v3 * c1);
            });
    } else {
        gemm_frag(g_Xf, g_WvF, rt, bx - 20, 32, smem,
            [&](int row, int col, float v0, float v1, float v2, float v3) {
                int kvh = col >> 6, dcol = col & 63;
                storeV16(kvh, row,     dcol,     f2fp16(v0));
                storeV16(kvh, row,     dcol + 1, f2fp16(v1));
                storeV16(kvh, row + 8, dcol,     f2fp16(v2));
                storeV16(kvh, row + 8, dcol + 1, f2fp16(v3));
            });
    }
}

// Output projection: out = g_Of @ WoF, fp32 result. grid (16, 16).
__global__ __launch_bounds__(256) void gemm_out(float* __restrict__ out)
{
    extern __shared__ char smem[];
    gemm_frag(g_Of, g_WoF, blockIdx.y, blockIdx.x, 32, smem,
        [&](int row, int col, float v0, float v1, float v2, float v3) {
            *(float2*)&out[(size_t)row * D_MODEL + col]       = make_float2(v0, v1);
            *(float2*)&out[(size_t)(row + 8) * D_MODEL + col] = make_float2(v2, v3);
        });
}

// ---------------------------------------------------------------------------
// FlashAttention-2, all-fp16 MMAs, base-2 softmax, zero shuffles,
// 3-stage cp.async pipeline. grid (32, H_KV, 4), 128 threads.
// ---------------------------------------------------------------------------
#define ATTN_SMEM (3 * 4096 * 4)   // 3 stages x (K 8KB + V 8KB)

__global__ __launch_bounds__(128) void attn_mma()
{
    extern __shared__ uint32_t sm[];

    const int kvh = blockIdx.y;
    const int tid = threadIdx.x;
    const int lane = tid & 31;
    const int w    = tid >> 5;
    const int g    = lane >> 2;
    const int t    = lane & 3;
    const int h    = kvh * REPEATS + blockIdx.z;
    const int qr0  = blockIdx.x * 64 + w * 16;
    const int tile0 = blockIdx.x;

    uint32_t qf[4][4];
    {
        const uint32_t* q0 = g_Qh + (size_t)qr0 * 512 + h * 32;
        #pragma unroll
        for (int kf = 0; kf < 4; kf++) {
            qf[kf][0] = q0[(size_t)g       * 512 + kf * 8 + t];
            qf[kf][1] = q0[(size_t)(g + 8) * 512 + kf * 8 + t];
            qf[kf][2] = q0[(size_t)g       * 512 + kf * 8 + t + 4];
            qf[kf][3] = q0[(size_t)(g + 8) * 512 + kf * 8 + t + 4];
        }
    }

    float m0 = -INFINITY, m1 = -INFINITY, l0 = 0.0f, l1 = 0.0f;
    float o[8][4];
    #pragma unroll
    for (int j = 0; j < 8; j++)
        #pragma unroll
        for (int r = 0; r < 4; r++) o[j][r] = 0.0f;

    auto issue = [&](int it, int stg) {
        int tile = (tile0 + it) & 31;
        const uint4* ks = (const uint4*)(g_KFb + (size_t)(kvh * 32 + tile) * 2048);
        const uint4* vs = (const uint4*)(g_VFh + (size_t)(kvh * 32 + tile) * 2048);
        uint32_t* dK = sm + stg * 4096;
        uint32_t* dV = dK + 2048;
        #pragma unroll
        for (int p = 0; p < 4; p++) {
            int i = tid + p * 128;
            cp16(&dK[i * 4], &ks[i]);
            cp16(&dV[i * 4], &vs[i]);
        }
        CP_COMMIT();
    };

    issue(0, 0);
    issue(1, 1);
    for (int it = 0; it < 32; it++) {
        const int stg = it % 3;
        CP_WAIT_1();
        __syncthreads();

        const uint2* KFs = (const uint2*)(sm + stg * 4096);
        const uint2* VFs = (const uint2*)(sm + stg * 4096 + 2048);

        float s[8][4];
        #pragma unroll
        for (int j = 0; j < 8; j++)
            #pragma unroll
            for (int r = 0; r < 4; r++) s[j][r] = 0.0f;
        #pragma unroll
        for (int kf = 0; kf < 4; kf++) {
            #pragma unroll
            for (int j = 0; j < 8; j++) {
                uint2 b = KFs[(j * 4 + kf) * 32 + lane];
                mma_f16(s[j], qf[kf][0], qf[kf][1], qf[kf][2], qf[kf][3], b.x, b.y);
            }
        }

        float tm0 = -INFINITY, tm1 = -INFINITY;
        #pragma unroll
        for (int j = 0; j < 8; j++) {
            tm0 = fmaxf(tm0, fmaxf(s[j][0], s[j][1]));
            tm1 = fmaxf(tm1, fmaxf(s[j][2], s[j][3]));
        }
        #pragma unroll
        for (int off = 1; off < 4; off <<= 1) {
            tm0 = fmaxf(tm0, __shfl_xor_sync(0xFFFFFFFF, tm0, off));
            tm1 = fmaxf(tm1, __shfl_xor_sync(0xFFFFFFFF, tm1, off));
        }
        float mn0 = fmaxf(m0, tm0), mn1 = fmaxf(m1, tm1);
        float c0 = ex2f(m0 - mn0), c1 = ex2f(m1 - mn1);
        l0 *= c0; l1 *= c1;
        #pragma unroll
        for (int j = 0; j < 8; j++) {
            o[j][0] *= c0; o[j][1] *= c0;
            o[j][2] *= c1; o[j][3] *= c1;
        }
        m0 = mn0; m1 = mn1;

        #pragma unroll
        for (int kbl = 0; kbl < 4; kbl++) {
            float pa0 = ex2f(s[2 * kbl][0] - mn0),     pa1 = ex2f(s[2 * kbl][1] - mn0);
            float pa2 = ex2f(s[2 * kbl][2] - mn1),     pa3 = ex2f(s[2 * kbl][3] - mn1);
            float pb0 = ex2f(s[2 * kbl + 1][0] - mn0), pb1 = ex2f(s[2 * kbl + 1][1] - mn0);
            float pb2 = ex2f(s[2 * kbl + 1][2] - mn1), pb3 = ex2f(s[2 * kbl + 1][3] - mn1);
            l0 += pa0 + pa1 + pb0 + pb1;
            l1 += pa2 + pa3 + pb2 + pb3;
            uint32_t a0 = packh2(pa0, pa1);
            uint32_t a1 = packh2(pa2, pa3);
            uint32_t a2 = packh2(pb0, pb1);
            uint32_t a3 = packh2(pb2, pb3);
            #pragma unroll
            for (int j = 0; j < 8; j++) {
                uint2 vv = VFs[(kbl * 8 + j) * 32 + lane];
                mma_f16(o[j], a0, a1, a2, a3, vv.x, vv.y);
            }
        }

        if (it + 2 < 32) issue(it + 2, (it + 2) % 3);
        else CP_COMMIT();
    }

    #pragma unroll
    for (int off = 1; off < 4; off <<= 1) {
        l0 += __shfl_xor_sync(0xFFFFFFFF, l0, off);
        l1 += __shfl_xor_sync(0xFFFFFFFF, l1, off);
    }
    float inv0 = 1.0f / l0, inv1 = 1.0f / l1;
    const int rt = qr0 >> 7;
    const int mb = (qr0 >> 4) & 7;
    uint4* of4 = (uint4*)g_Of;
    #pragma unroll
    for (int jp = 0; jp < 4; jp++) {
        int j0 = 2 * jp, j1 = j0 + 1;
        uint4 a;
        a.x = packh2(o[j0][0] * inv0, o[j0][1] * inv0);
        a.y = packh2(o[j0][2] * inv1, o[j0][3] * inv1);
        a.z = packh2(o[j1][0] * inv0, o[j1][1] * inv0);
        a.w = packh2(o[j1][2] * inv1, o[j1][3] * inv1);
        int kt = h * 2 + (jp >> 1), kb = jp & 1;
        of4[((size_t)(rt * 32 + kt)) * 512 + (mb * 2 + kb) * 32 + lane] = a;
    }
}

// ---------------------------------------------------------------------------
// Launcher
// ---------------------------------------------------------------------------
extern "C" void kernel_launch(void* const* d_in, const int* in_sizes, int n_in,
                              void* d_out, int out_size)
{
    const float* x    = (const float*)d_in[0];
    const float* fcos = (const float*)d_in[1];
    const float* fsin = (const float*)d_in[2];
    const float* Wq   = (const float*)d_in[3];
    const float* Wk   = (const float*)d_in[4];
    const float* Wv   = (const float*)d_in[5];
    const float* Wo   = (const float*)d_in[6];
    float* out = (float*)d_out;

    static bool init = false;
    if (!init) {
        cudaFuncSetAttribute(qkv_gemm, cudaFuncAttributeMaxDynamicSharedMemorySize, GEMM_SMEM);
        cudaFuncSetAttribute(gemm_out, cudaFuncAttributeMaxDynamicSharedMemorySize, GEMM_SMEM);
        cudaFuncSetAttribute(attn_mma, cudaFuncAttributeMaxDynamicSharedMemorySize, ATTN_SMEM);
        init = true;
    }

    // 1. prep: x -> fp16 A-frag; weights -> fp16 B-frag
    prep_all<<<1480, 256>>>(x, Wq, Wk, Wv, Wo);

    // 2. QKV projection + RoPE (3-stage pipeline)
    qkv_gemm<<<dim3(24, N_TOK / 128), 256, GEMM_SMEM>>>(fcos, fsin);

    // 3. Attention (3-stage pipeline)
    attn_mma<<<dim3(N_TOK / 64, H_KV, REPEATS), 128, ATTN_SMEM>>>();

    // 4. Output projection (3-stage pipeline)
    gemm_out<<<dim3(D_MODEL / 64, N_TOK / 128), 256, GEMM_SMEM>>>(out);
}